// round 6
// baseline (speedup 1.0000x reference)
#include <cuda_runtime.h>
#include <cuda_fp16.h>
#include <math.h>

#define BB_   32
#define DIM_  256
#define HEADS_ 8
#define KD_   16
#define DV_   64
#define NHKD_ 128
#define DH_   512
#define QKVO_ 768
#define WW_   28
#define NN_   784
#define EPSBN 1e-5f
#define SCALE_ 0.25f
#define LOG2E_ 1.4426950408889634f

// ---------------- scratch (fp16 intermediates) ----------------
__device__ __half g_qkv[(size_t)BB_ * QKVO_ * NN_];
__device__ __half g_qdw[(size_t)BB_ * NHKD_ * NN_];
__device__ __half g_att[(size_t)BB_ * DH_ * NN_];
__device__ __half g_x16[(size_t)BB_ * DIM_ * NN_];
__device__ __half g_wqkv[QKVO_ * DIM_];
__device__ __half g_wproj[DIM_ * DH_];

// ---------------- helpers ----------------
__device__ __forceinline__ float ex2f(float x) {
    float y; asm("ex2.approx.ftz.f32 %0, %1;" : "=f"(y) : "f"(x)); return y;
}
__device__ __forceinline__ unsigned fh2(float lo, float hi) {
    __half2 h = __floats2half2_rn(lo, hi);
    return *reinterpret_cast<unsigned*>(&h);
}
__device__ __forceinline__ unsigned h2u(__half2 h) {
    return *reinterpret_cast<unsigned*>(&h);
}
__device__ __forceinline__ void mma16(float4& c, const uint4& a, unsigned b0, unsigned b1) {
    asm volatile(
        "mma.sync.aligned.m16n8k16.row.col.f32.f16.f16.f32 "
        "{%0,%1,%2,%3},{%4,%5,%6,%7},{%8,%9},{%0,%1,%2,%3};"
        : "+f"(c.x), "+f"(c.y), "+f"(c.z), "+f"(c.w)
        : "r"(a.x), "r"(a.y), "r"(a.z), "r"(a.w), "r"(b0), "r"(b1));
}

// =====================================================================
// x fp32 -> fp16 transcode
// =====================================================================
__global__ void __launch_bounds__(256) x_to_half(const float4* __restrict__ in,
                                                 uint2* __restrict__ out, int n4)
{
    const int i = blockIdx.x * 256 + threadIdx.x;
    if (i >= n4) return;
    float4 v = in[i];
    out[i] = make_uint2(fh2(v.x, v.y), fh2(v.z, v.w));
}

// =====================================================================
// Weight prepack: row-major fp32 [M,K] -> fp16 m16n8k16 A-fragment layout.
// =====================================================================
__global__ void prepack_w(const float* __restrict__ W, __half* __restrict__ P,
                          int M, int K)
{
    const int i = blockIdx.x * 256 + threadIdx.x;
    if (i >= M * K) return;
    const int m = i / K, k = i % K;
    const int mi = m >> 4, r = m & 15, g2 = r & 7, hf = r >> 3;
    const int ks = k >> 4, kk = k & 15;
    const int tgw = (kk >> 1) & 3, kh = kk >> 3, lo = kk & 1;
    P[((size_t)((mi * (K >> 4) + ks) * 32) + g2 * 4 + tgw) * 8 + (hf + 2 * kh) * 2 + lo]
        = __float2half_rn(W[i]);
}

// =====================================================================
// fp16 GEMM + BN. A prepacked (global->reg), B fp16 staged to B-frag smem,
// double-buffered. Block 128(M) x 112(N) x 32(K), 256 thr, warp 32x56.
// =====================================================================
template<bool OUT_HALF>
__global__ void __launch_bounds__(256, 2) gemm_f16(
    const uint4* __restrict__ Apk,
    const __half* __restrict__ Bsrc,
    void*        __restrict__ Cb,
    const float* __restrict__ gg, const float* __restrict__ bbp,
    const float* __restrict__ mmp, const float* __restrict__ vvp,
    int M, int N, int K)
{
    const int n0 = blockIdx.y * 112;
    const int z  = blockIdx.z;
    const __half* Bz = Bsrc + (size_t)z * K * N;

    __shared__ unsigned Bf[2][14 * 32 * 4];

    const int t    = threadIdx.x;
    const int lane = t & 31, wid = t >> 5;
    const int g    = lane >> 2, tg = lane & 3;
    const int wm   = wid >> 1, wn = wid & 1;
    const int nkt  = K >> 5;
    const int kt16 = K >> 4;

    float4 acc[2][7];
    #pragma unroll
    for (int i = 0; i < 2; ++i)
        #pragma unroll
        for (int j = 0; j < 7; ++j) acc[i][j] = make_float4(0.f, 0.f, 0.f, 0.f);

    // staging: 448 tasks = 16 k-pairs x 28 n4-groups
    int pj[2], n4j[2]; bool okj[2];
    int tgt[2][4];
    #pragma unroll
    for (int j = 0; j < 2; ++j) {
        const int idx = t + 256 * j;
        okj[j] = idx < 448;
        pj[j]  = okj[j] ? idx / 28 : 0;
        n4j[j] = okj[j] ? idx % 28 : 0;
        const int p = pj[j];
        #pragma unroll
        for (int e = 0; e < 4; ++e) {
            const int n = n4j[j] * 4 + e;
            tgt[j][e] = (((n >> 3) * 32 + (n & 7) * 4 + (p & 3)) * 2 + (p >> 3)) * 2
                        + ((p >> 2) & 1);
        }
    }

    unsigned uv[2][4];
    auto loadB = [&](int kt) {
        #pragma unroll
        for (int j = 0; j < 2; ++j) {
            if (!okj[j]) continue;
            const int k = kt * 32 + 2 * pj[j];
            const int nc = n0 + n4j[j] * 4;
            uint2 r0 = *reinterpret_cast<const uint2*>(&Bz[(size_t)k * N + nc]);
            uint2 r1 = *reinterpret_cast<const uint2*>(&Bz[(size_t)(k + 1) * N + nc]);
            __half2 A0 = *reinterpret_cast<__half2*>(&r0.x);
            __half2 A1 = *reinterpret_cast<__half2*>(&r0.y);
            __half2 B0 = *reinterpret_cast<__half2*>(&r1.x);
            __half2 B1 = *reinterpret_cast<__half2*>(&r1.y);
            uv[j][0] = h2u(__lows2half2(A0, B0));
            uv[j][1] = h2u(__highs2half2(A0, B0));
            uv[j][2] = h2u(__lows2half2(A1, B1));
            uv[j][3] = h2u(__highs2half2(A1, B1));
        }
    };
    auto stsB = [&](unsigned* buf) {
        #pragma unroll
        for (int j = 0; j < 2; ++j)
            if (okj[j]) {
                #pragma unroll
                for (int e = 0; e < 4; ++e) buf[tgt[j][e]] = uv[j][e];
            }
    };

    const int mi0 = blockIdx.x * 8 + wm * 2;

    loadB(0); stsB(Bf[0]);
    if (nkt > 1) loadB(1);

    for (int kt = 0; kt < nkt; ++kt) {
        uint4 af[2][2];
        #pragma unroll
        for (int mt = 0; mt < 2; ++mt)
            #pragma unroll
            for (int ks = 0; ks < 2; ++ks)
                af[mt][ks] = Apk[(size_t)((mi0 + mt) * kt16 + kt * 2 + ks) * 32 + lane];

        __syncthreads();
        if (kt + 1 < nkt) {
            stsB(Bf[(kt + 1) & 1]);
            if (kt + 2 < nkt) loadB(kt + 2);
        }

        const unsigned* buf = Bf[kt & 1];
        #pragma unroll
        for (int nt = 0; nt < 7; ++nt) {
            uint4 b4 = *reinterpret_cast<const uint4*>(
                &buf[((wn * 7 + nt) * 32 + lane) * 4]);
            mma16(acc[0][nt], af[0][0], b4.x, b4.y);
            mma16(acc[0][nt], af[0][1], b4.z, b4.w);
            mma16(acc[1][nt], af[1][0], b4.x, b4.y);
            mma16(acc[1][nt], af[1][1], b4.z, b4.w);
        }
    }

    // BN epilogue
    #pragma unroll
    for (int mt = 0; mt < 2; ++mt) {
        const int r0 = (mi0 + mt) * 16 + g;
        const int r1 = r0 + 8;
        const float s0 = gg[r0] * rsqrtf(vvp[r0] + EPSBN);
        const float t0 = bbp[r0] - mmp[r0] * s0;
        const float s1 = gg[r1] * rsqrtf(vvp[r1] + EPSBN);
        const float t1 = bbp[r1] - mmp[r1] * s1;
        #pragma unroll
        for (int nt = 0; nt < 7; ++nt) {
            const int c = n0 + wn * 56 + nt * 8 + tg * 2;
            float4 a = acc[mt][nt];
            if (OUT_HALF) {
                __half* C = (__half*)Cb + (size_t)z * M * N;
                *reinterpret_cast<unsigned*>(&C[(size_t)r0 * N + c]) =
                    fh2(a.x * s0 + t0, a.y * s0 + t0);
                *reinterpret_cast<unsigned*>(&C[(size_t)r1 * N + c]) =
                    fh2(a.z * s1 + t1, a.w * s1 + t1);
            } else {
                float* C = (float*)Cb + (size_t)z * M * N;
                *reinterpret_cast<float2*>(&C[(size_t)r0 * N + c]) =
                    make_float2(a.x * s0 + t0, a.y * s0 + t0);
                *reinterpret_cast<float2*>(&C[(size_t)r1 * N + c]) =
                    make_float2(a.z * s1 + t1, a.w * s1 + t1);
            }
        }
    }
}

// =====================================================================
// Depthwise 3x3 + BN; output scaled by SCALE*LOG2E, fp16
// =====================================================================
__global__ void __launch_bounds__(256) dwconv_kernel(
    const float* __restrict__ dw_w,
    const float* __restrict__ gg, const float* __restrict__ bb,
    const float* __restrict__ mm, const float* __restrict__ vv)
{
    const int bc = blockIdx.x;
    const int b  = bc >> 7;
    const int c  = bc & 127;
    const int t  = threadIdx.x;

    __shared__ float tile[30][30];
    for (int i = t; i < 900; i += 256) (&tile[0][0])[i] = 0.f;
    __syncthreads();

    const __half* in = &g_qkv[((size_t)b * QKVO_ + c) * NN_];
    for (int n = t; n < NN_; n += 256)
        tile[n / WW_ + 1][n % WW_ + 1] = __half2float(in[n]);
    __syncthreads();

    float wv[9];
    #pragma unroll
    for (int k = 0; k < 9; ++k) wv[k] = dw_w[c * 9 + k];
    const float s  = gg[c] * rsqrtf(vv[c] + EPSBN);
    const float tt = bb[c] - mm[c] * s;
    const float qs = SCALE_ * LOG2E_;

    __half* outp = &g_qdw[((size_t)b * NHKD_ + c) * NN_];
    for (int n = t; n < NN_; n += 256) {
        const int y = n / WW_, x = n % WW_;
        float a = 0.f;
        #pragma unroll
        for (int ky = 0; ky < 3; ++ky)
            #pragma unroll
            for (int kx = 0; kx < 3; ++kx)
                a = fmaf(tile[y + ky][x + kx], wv[ky * 3 + kx], a);
        outp[n] = __float2half_rn((a * s + tt) * qs);
    }
}

// =====================================================================
// Flash attention, fp16 m16n8k16. 112 queries (7 warps), key chunks of 112
// (= 4 image rows, mask-free, PV k exact 7x16). P in registers only.
// Double-buffered K/V, exp2 softmax, relu folded into fp16 output.
// =====================================================================
__global__ void __launch_bounds__(224, 2) attn_f16(const float* __restrict__ ab)
{
    __shared__ unsigned Qf[7 * 32 * 4];      // A-frag uint4 per (mi,lane)
    __shared__ unsigned Kf[2][14 * 32 * 2];  // B-frag uint2 per (nt,lane)
    __shared__ unsigned Vf[2][8 * 32 * 16];  // (nt*32+lane)*16 + ks*2 + kh (14 used)
    __shared__ float biasS[784];

    const int qt = blockIdx.x, h = blockIdx.y, b = blockIdx.z;
    const int q0 = qt * 112;
    const int t = threadIdx.x, lane = t & 31, wid = t >> 5;
    const int g = lane >> 2, tg = lane & 3;

    for (int i = t; i < 784; i += 224) biasS[i] = ab[h * 784 + i] * LOG2E_;

    // ---- Q staging (224 tasks): d-pair p = t/28, q4 = t%28 ----
    {
        const int p = t / 28, q4 = t % 28;
        const __half* qrow = g_qdw + ((size_t)b * NHKD_ + h * KD_ + 2 * p) * NN_
                             + q0 + q4 * 4;
        uint2 r0 = *reinterpret_cast<const uint2*>(qrow);
        uint2 r1 = *reinterpret_cast<const uint2*>(qrow + NN_);
        __half2 A0 = *reinterpret_cast<__half2*>(&r0.x);
        __half2 A1 = *reinterpret_cast<__half2*>(&r0.y);
        __half2 B0 = *reinterpret_cast<__half2*>(&r1.x);
        __half2 B1 = *reinterpret_cast<__half2*>(&r1.y);
        unsigned u[4] = { h2u(__lows2half2(A0, B0)), h2u(__highs2half2(A0, B0)),
                          h2u(__lows2half2(A1, B1)), h2u(__highs2half2(A1, B1)) };
        #pragma unroll
        for (int e = 0; e < 4; ++e) {
            const int q = q4 * 4 + e;
            const int mi = q >> 4, r = q & 15;
            Qf[(mi * 32 + (r & 7) * 4 + (p & 3)) * 4 + ((r >> 3) + 2 * (p >> 2))] = u[e];
        }
    }

    const int qa = q0 + wid * 16 + g;
    const int qya = qa / WW_, qxa = qa % WW_;
    const int qyb = (qa + 8) / WW_, qxb = (qa + 8) % WW_;

    float M0 = -1e30f, M1 = -1e30f, L0 = 0.f, L1 = 0.f;
    float4 O[8];
    #pragma unroll
    for (int i = 0; i < 8; ++i) O[i] = make_float4(0.f, 0.f, 0.f, 0.f);

    const __half* kbase = &g_qkv[((size_t)b * QKVO_ + NHKD_ + h * KD_) * NN_];
    const __half* vbase = &g_qkv[((size_t)b * QKVO_ + 2 * NHKD_ + h * DV_) * NN_];

    // K staging: 224 tasks exactly: d-pair kp = t/28, kn4 = t%28
    const int kp = t / 28, kn4 = t % 28;
    int ktgt[4];
    #pragma unroll
    for (int e = 0; e < 4; ++e) {
        const int n = kn4 * 4 + e;
        ktgt[e] = ((n >> 3) * 32 + (n & 7) * 4 + (kp & 3)) * 2 + (kp >> 2);
    }
    // V staging: 896 tasks (4/thread): d = idx/14, n8 = idx%14 (uint4 = 8 keys)
    int vd[4], vn8[4], vtb[4];
    #pragma unroll
    for (int j = 0; j < 4; ++j) {
        const int idx = t + 224 * j;
        vd[j] = idx / 14; vn8[j] = idx % 14;
        vtb[j] = ((vd[j] >> 3) * 32 + (vd[j] & 7) * 4) * 16
                 + (vn8[j] >> 1) * 2 + (vn8[j] & 1);
    }

    unsigned ku[4];
    uint4 vreg[4];
    auto loadKV = [&](int c) {
        const int n0c = c * 112;
        const __half* kr = kbase + (size_t)(2 * kp) * NN_ + n0c + kn4 * 4;
        uint2 r0 = *reinterpret_cast<const uint2*>(kr);
        uint2 r1 = *reinterpret_cast<const uint2*>(kr + NN_);
        __half2 A0 = *reinterpret_cast<__half2*>(&r0.x);
        __half2 A1 = *reinterpret_cast<__half2*>(&r0.y);
        __half2 B0 = *reinterpret_cast<__half2*>(&r1.x);
        __half2 B1 = *reinterpret_cast<__half2*>(&r1.y);
        ku[0] = h2u(__lows2half2(A0, B0));  ku[1] = h2u(__highs2half2(A0, B0));
        ku[2] = h2u(__lows2half2(A1, B1)); ku[3] = h2u(__highs2half2(A1, B1));
        #pragma unroll
        for (int j = 0; j < 4; ++j)
            vreg[j] = *reinterpret_cast<const uint4*>(
                &vbase[(size_t)vd[j] * NN_ + n0c + vn8[j] * 8]);
    };
    auto stsKV = [&](unsigned* kb, unsigned* vb) {
        #pragma unroll
        for (int e = 0; e < 4; ++e) kb[ktgt[e]] = ku[e];
        #pragma unroll
        for (int j = 0; j < 4; ++j) {
            vb[vtb[j]]          = vreg[j].x;   // tgw 0
            vb[vtb[j] + 16]     = vreg[j].y;   // tgw 1
            vb[vtb[j] + 32]     = vreg[j].z;   // tgw 2
            vb[vtb[j] + 48]     = vreg[j].w;   // tgw 3
        }
    };

    loadKV(0);
    stsKV(Kf[0], Vf[0]);
    loadKV(1);
    __syncthreads();

    const uint4 qfrag = *reinterpret_cast<const uint4*>(&Qf[(wid * 32 + lane) * 4]);

    for (int c = 0; c < 7; ++c) {
        if (c + 1 < 7) {
            stsKV(Kf[(c + 1) & 1], Vf[(c + 1) & 1]);
            if (c + 2 < 7) loadKV(c + 2);
        }
        const unsigned* Kb = Kf[c & 1];
        const unsigned* Vb = Vf[c & 1];

        // ---- S = Q.K : 14 mma ----
        float4 S[14];
        #pragma unroll
        for (int i = 0; i < 14; ++i) S[i] = make_float4(0.f, 0.f, 0.f, 0.f);
        #pragma unroll
        for (int nt = 0; nt < 14; ++nt) {
            uint2 kb = *reinterpret_cast<const uint2*>(&Kb[(nt * 32 + lane) * 2]);
            mma16(S[nt], qfrag, kb.x, kb.y);
        }

        // ---- bias (chunk = image rows 4c..4c+3) ----
        int bya[4], byb[4];
        #pragma unroll
        for (int r = 0; r < 4; ++r) {
            bya[r] = abs(qya - (4 * c + r)) * WW_;
            byb[r] = abs(qyb - (4 * c + r)) * WW_;
        }
        #pragma unroll
        for (int nt = 0; nt < 14; ++nt) {
            const int c0 = nt * 8 + tg * 2, c1 = c0 + 1;
            const int r0 = c0 / 28, nx0 = c0 - r0 * 28;
            const int r1 = c1 / 28, nx1 = c1 - r1 * 28;
            S[nt].x += biasS[bya[r0] + abs(qxa - nx0)];
            S[nt].y += biasS[bya[r1] + abs(qxa - nx1)];
            S[nt].z += biasS[byb[r0] + abs(qxb - nx0)];
            S[nt].w += biasS[byb[r1] + abs(qxb - nx1)];
        }

        // ---- online softmax (log2 domain) ----
        float mx0 = -1e30f, mx1 = -1e30f;
        #pragma unroll
        for (int nt = 0; nt < 14; ++nt) {
            mx0 = fmaxf(mx0, fmaxf(S[nt].x, S[nt].y));
            mx1 = fmaxf(mx1, fmaxf(S[nt].z, S[nt].w));
        }
        mx0 = fmaxf(mx0, __shfl_xor_sync(0xffffffffu, mx0, 1));
        mx0 = fmaxf(mx0, __shfl_xor_sync(0xffffffffu, mx0, 2));
        mx1 = fmaxf(mx1, __shfl_xor_sync(0xffffffffu, mx1, 1));
        mx1 = fmaxf(mx1, __shfl_xor_sync(0xffffffffu, mx1, 2));
        const float nM0 = fmaxf(M0, mx0), nM1 = fmaxf(M1, mx1);
        const float cor0 = ex2f(M0 - nM0), cor1 = ex2f(M1 - nM1);
        M0 = nM0; M1 = nM1;
        float rs0 = 0.f, rs1 = 0.f;
        #pragma unroll
        for (int nt = 0; nt < 14; ++nt) {
            S[nt].x = ex2f(S[nt].x - nM0); rs0 += S[nt].x;
            S[nt].y = ex2f(S[nt].y - nM0); rs0 += S[nt].y;
            S[nt].z = ex2f(S[nt].z - nM1); rs1 += S[nt].z;
            S[nt].w = ex2f(S[nt].w - nM1); rs1 += S[nt].w;
        }
        rs0 += __shfl_xor_sync(0xffffffffu, rs0, 1);
        rs0 += __shfl_xor_sync(0xffffffffu, rs0, 2);
        rs1 += __shfl_xor_sync(0xffffffffu, rs1, 1);
        rs1 += __shfl_xor_sync(0xffffffffu, rs1, 2);
        L0 = L0 * cor0 + rs0;
        L1 = L1 * cor1 + rs1;
        #pragma unroll
        for (int i = 0; i < 8; ++i) {
            O[i].x *= cor0; O[i].y *= cor0;
            O[i].z *= cor1; O[i].w *= cor1;
        }

        // ---- P: registers only (7 exact k16 fragments) ----
        uint4 Pk[7];
        #pragma unroll
        for (int ks = 0; ks < 7; ++ks)
            Pk[ks] = make_uint4(fh2(S[2 * ks].x,     S[2 * ks].y),
                                fh2(S[2 * ks].z,     S[2 * ks].w),
                                fh2(S[2 * ks + 1].x, S[2 * ks + 1].y),
                                fh2(S[2 * ks + 1].z, S[2 * ks + 1].w));

        // ---- O += P.V : 56 mma ----
        #pragma unroll
        for (int nt = 0; nt < 8; ++nt) {
            const unsigned* vb = &Vb[(nt * 32 + lane) * 16];
            uint4 v0 = *reinterpret_cast<const uint4*>(vb);
            uint4 v1 = *reinterpret_cast<const uint4*>(vb + 4);
            uint4 v2 = *reinterpret_cast<const uint4*>(vb + 8);
            uint2 v3 = *reinterpret_cast<const uint2*>(vb + 12);
            mma16(O[nt], Pk[0], v0.x, v0.y);
            mma16(O[nt], Pk[1], v0.z, v0.w);
            mma16(O[nt], Pk[2], v1.x, v1.y);
            mma16(O[nt], Pk[3], v1.z, v1.w);
            mma16(O[nt], Pk[4], v2.x, v2.y);
            mma16(O[nt], Pk[5], v2.z, v2.w);
            mma16(O[nt], Pk[6], v3.x, v3.y);
        }
        __syncthreads();
    }

    // ---- normalize + relu + fp16 store ----
    const float i0 = 1.f / L0, i1 = 1.f / L1;
    __half* obase = g_att + ((size_t)b * DH_ + h * DV_) * NN_;
    #pragma unroll
    for (int nt = 0; nt < 8; ++nt) {
        const int d0 = nt * 8 + tg * 2;
        obase[(size_t)d0 * NN_ + qa]           = __float2half_rn(fmaxf(O[nt].x * i0, 0.f));
        obase[(size_t)(d0 + 1) * NN_ + qa]     = __float2half_rn(fmaxf(O[nt].y * i0, 0.f));
        obase[(size_t)d0 * NN_ + qa + 8]       = __float2half_rn(fmaxf(O[nt].z * i1, 0.f));
        obase[(size_t)(d0 + 1) * NN_ + qa + 8] = __float2half_rn(fmaxf(O[nt].w * i1, 0.f));
    }
}

// =====================================================================
// launch
// =====================================================================
extern "C" void kernel_launch(void* const* d_in, const int* in_sizes, int n_in,
                              void* d_out, int out_size)
{
    const float* x      = (const float*)d_in[0];
    const float* qkv_w  = (const float*)d_in[1];
    const float* qkv_g  = (const float*)d_in[2];
    const float* qkv_b  = (const float*)d_in[3];
    const float* qkv_m  = (const float*)d_in[4];
    const float* qkv_v  = (const float*)d_in[5];
    const float* dw_w   = (const float*)d_in[6];
    const float* dw_g   = (const float*)d_in[7];
    const float* dw_b   = (const float*)d_in[8];
    const float* dw_m   = (const float*)d_in[9];
    const float* dw_v   = (const float*)d_in[10];
    const float* ab     = (const float*)d_in[11];
    const float* proj_w = (const float*)d_in[12];
    const float* proj_g = (const float*)d_in[13];
    const float* proj_b = (const float*)d_in[14];
    const float* proj_m = (const float*)d_in[15];
    const float* proj_v = (const float*)d_in[16];
    float* out = (float*)d_out;

    void *p_qkv, *p_att, *p_x16, *p_wqkv, *p_wproj;
    cudaGetSymbolAddress(&p_qkv, g_qkv);
    cudaGetSymbolAddress(&p_att, g_att);
    cudaGetSymbolAddress(&p_x16, g_x16);
    cudaGetSymbolAddress(&p_wqkv, g_wqkv);
    cudaGetSymbolAddress(&p_wproj, g_wproj);

    // 0) prepack + transcode
    prepack_w<<<(QKVO_ * DIM_ + 255) / 256, 256>>>(qkv_w, (__half*)p_wqkv, QKVO_, DIM_);
    prepack_w<<<(DIM_ * DH_ + 255) / 256, 256>>>(proj_w, (__half*)p_wproj, DIM_, DH_);
    {
        const int n4 = BB_ * DIM_ * NN_ / 4;
        x_to_half<<<(n4 + 255) / 256, 256>>>((const float4*)x, (uint2*)p_x16, n4);
    }

    // 1) QKV 1x1 + BN : fp16 in -> fp16 out
    gemm_f16<true><<<dim3(QKVO_ / 128, NN_ / 112, BB_), 256>>>(
        (const uint4*)p_wqkv, (const __half*)p_x16, p_qkv,
        qkv_g, qkv_b, qkv_m, qkv_v, QKVO_, NN_, DIM_);

    // 2) depthwise 3x3 + BN (scaled for attention)
    dwconv_kernel<<<BB_ * NHKD_, 256>>>(dw_w, dw_g, dw_b, dw_m, dw_v);

    // 3) attention (relu folded in, fp16 out)
    attn_f16<<<dim3(NN_ / 112, HEADS_, BB_), 224>>>(ab);

    // 4) proj 1x1 + BN : fp16 in -> fp32 out
    gemm_f16<false><<<dim3(DIM_ / 128, NN_ / 112, BB_), 256>>>(
        (const uint4*)p_wproj, (const __half*)p_att, out,
        proj_g, proj_b, proj_m, proj_v, DIM_, NN_, DH_);
}

// round 7
// speedup vs baseline: 1.1522x; 1.1522x over previous
#include <cuda_runtime.h>
#include <cuda_fp16.h>
#include <math.h>

#define BB_   32
#define DIM_  256
#define HEADS_ 8
#define KD_   16
#define DV_   64
#define NHKD_ 128
#define DH_   512
#define QKVO_ 768
#define WW_   28
#define NN_   784
#define EPSBN 1e-5f
#define SCALE_ 0.25f
#define LOG2E_ 1.4426950408889634f

// ---------------- scratch (fp16 intermediates) ----------------
__device__ __half g_qkv[(size_t)BB_ * QKVO_ * NN_];
__device__ __half g_qdw[(size_t)BB_ * NHKD_ * NN_];
__device__ __half g_att[(size_t)BB_ * DH_ * NN_];
__device__ __half g_x16[(size_t)BB_ * DIM_ * NN_];
__device__ __half g_wqkv[QKVO_ * DIM_];
__device__ __half g_wproj[DIM_ * DH_];

// ---------------- helpers ----------------
__device__ __forceinline__ float ex2f(float x) {
    float y; asm("ex2.approx.ftz.f32 %0, %1;" : "=f"(y) : "f"(x)); return y;
}
__device__ __forceinline__ unsigned fh2(float lo, float hi) {
    __half2 h = __floats2half2_rn(lo, hi);
    return *reinterpret_cast<unsigned*>(&h);
}
__device__ __forceinline__ unsigned h2u(__half2 h) {
    return *reinterpret_cast<unsigned*>(&h);
}
__device__ __forceinline__ void mma16(float4& c, const uint4& a, unsigned b0, unsigned b1) {
    asm volatile(
        "mma.sync.aligned.m16n8k16.row.col.f32.f16.f16.f32 "
        "{%0,%1,%2,%3},{%4,%5,%6,%7},{%8,%9},{%0,%1,%2,%3};"
        : "+f"(c.x), "+f"(c.y), "+f"(c.z), "+f"(c.w)
        : "r"(a.x), "r"(a.y), "r"(a.z), "r"(a.w), "r"(b0), "r"(b1));
}

// =====================================================================
// x fp32 -> fp16 transcode
// =====================================================================
__global__ void __launch_bounds__(256) x_to_half(const float4* __restrict__ in,
                                                 uint2* __restrict__ out, int n4)
{
    const int i = blockIdx.x * 256 + threadIdx.x;
    if (i >= n4) return;
    float4 v = in[i];
    out[i] = make_uint2(fh2(v.x, v.y), fh2(v.z, v.w));
}

// =====================================================================
// Weight prepack: row-major fp32 [M,K] -> fp16 m16n8k16 A-fragment layout.
// =====================================================================
__global__ void prepack_w(const float* __restrict__ W, __half* __restrict__ P,
                          int M, int K)
{
    const int i = blockIdx.x * 256 + threadIdx.x;
    if (i >= M * K) return;
    const int m = i / K, k = i % K;
    const int mi = m >> 4, r = m & 15, g2 = r & 7, hf = r >> 3;
    const int ks = k >> 4, kk = k & 15;
    const int tgw = (kk >> 1) & 3, kh = kk >> 3, lo = kk & 1;
    P[((size_t)((mi * (K >> 4) + ks) * 32) + g2 * 4 + tgw) * 8 + (hf + 2 * kh) * 2 + lo]
        = __float2half_rn(W[i]);
}

// =====================================================================
// fp16 GEMM + BN. A prepacked, register double-buffered (prefetched one
// k-block ahead); B fp16 staged to B-frag smem, double-buffered.
// Block 128(M) x 112(N) x 32(K), 256 thr, warp 32x56.
// =====================================================================
template<bool OUT_HALF>
__global__ void __launch_bounds__(256, 2) gemm_f16(
    const uint4* __restrict__ Apk,
    const __half* __restrict__ Bsrc,
    void*        __restrict__ Cb,
    const float* __restrict__ gg, const float* __restrict__ bbp,
    const float* __restrict__ mmp, const float* __restrict__ vvp,
    int M, int N, int K)
{
    const int n0 = blockIdx.y * 112;
    const int z  = blockIdx.z;
    const __half* Bz = Bsrc + (size_t)z * K * N;

    __shared__ unsigned Bf[2][14 * 32 * 4];

    const int t    = threadIdx.x;
    const int lane = t & 31, wid = t >> 5;
    const int g    = lane >> 2, tg = lane & 3;
    const int wm   = wid >> 1, wn = wid & 1;
    const int nkt  = K >> 5;
    const int kt16 = K >> 4;

    float4 acc[2][7];
    #pragma unroll
    for (int i = 0; i < 2; ++i)
        #pragma unroll
        for (int j = 0; j < 7; ++j) acc[i][j] = make_float4(0.f, 0.f, 0.f, 0.f);

    // staging: 448 tasks = 16 k-pairs x 28 n4-groups
    int pj[2], n4j[2]; bool okj[2];
    int tgt[2][4];
    #pragma unroll
    for (int j = 0; j < 2; ++j) {
        const int idx = t + 256 * j;
        okj[j] = idx < 448;
        pj[j]  = okj[j] ? idx / 28 : 0;
        n4j[j] = okj[j] ? idx % 28 : 0;
        const int p = pj[j];
        #pragma unroll
        for (int e = 0; e < 4; ++e) {
            const int n = n4j[j] * 4 + e;
            tgt[j][e] = (((n >> 3) * 32 + (n & 7) * 4 + (p & 3)) * 2 + (p >> 3)) * 2
                        + ((p >> 2) & 1);
        }
    }

    unsigned uv[2][4];
    auto loadB = [&](int kt) {
        #pragma unroll
        for (int j = 0; j < 2; ++j) {
            if (!okj[j]) continue;
            const int k = kt * 32 + 2 * pj[j];
            const int nc = n0 + n4j[j] * 4;
            uint2 r0 = *reinterpret_cast<const uint2*>(&Bz[(size_t)k * N + nc]);
            uint2 r1 = *reinterpret_cast<const uint2*>(&Bz[(size_t)(k + 1) * N + nc]);
            __half2 A0 = *reinterpret_cast<__half2*>(&r0.x);
            __half2 A1 = *reinterpret_cast<__half2*>(&r0.y);
            __half2 B0 = *reinterpret_cast<__half2*>(&r1.x);
            __half2 B1 = *reinterpret_cast<__half2*>(&r1.y);
            uv[j][0] = h2u(__lows2half2(A0, B0));
            uv[j][1] = h2u(__highs2half2(A0, B0));
            uv[j][2] = h2u(__lows2half2(A1, B1));
            uv[j][3] = h2u(__highs2half2(A1, B1));
        }
    };
    auto stsB = [&](unsigned* buf) {
        #pragma unroll
        for (int j = 0; j < 2; ++j)
            if (okj[j]) {
                #pragma unroll
                for (int e = 0; e < 4; ++e) buf[tgt[j][e]] = uv[j][e];
            }
    };

    const int mi0 = blockIdx.x * 8 + wm * 2;

    // A fragments: register double-buffer, prefetched one k-block ahead
    uint4 af[2][2][2];
    auto loadA = [&](int kt, int buf) {
        #pragma unroll
        for (int mt = 0; mt < 2; ++mt)
            #pragma unroll
            for (int ks = 0; ks < 2; ++ks)
                af[buf][mt][ks] =
                    Apk[(size_t)((mi0 + mt) * kt16 + kt * 2 + ks) * 32 + lane];
    };

    loadA(0, 0);
    loadB(0); stsB(Bf[0]);
    if (nkt > 1) loadB(1);

    for (int kt = 0; kt < nkt; ++kt) {
        const int cur = kt & 1;
        if (kt + 1 < nkt) loadA(kt + 1, cur ^ 1);

        __syncthreads();
        if (kt + 1 < nkt) {
            stsB(Bf[cur ^ 1]);
            if (kt + 2 < nkt) loadB(kt + 2);
        }

        const unsigned* buf = Bf[cur];
        #pragma unroll
        for (int nt = 0; nt < 7; ++nt) {
            uint4 b4 = *reinterpret_cast<const uint4*>(
                &buf[((wn * 7 + nt) * 32 + lane) * 4]);
            mma16(acc[0][nt], af[cur][0][0], b4.x, b4.y);
            mma16(acc[0][nt], af[cur][0][1], b4.z, b4.w);
            mma16(acc[1][nt], af[cur][1][0], b4.x, b4.y);
            mma16(acc[1][nt], af[cur][1][1], b4.z, b4.w);
        }
    }

    // BN epilogue
    #pragma unroll
    for (int mt = 0; mt < 2; ++mt) {
        const int r0 = (mi0 + mt) * 16 + g;
        const int r1 = r0 + 8;
        const float s0 = gg[r0] * rsqrtf(vvp[r0] + EPSBN);
        const float t0 = bbp[r0] - mmp[r0] * s0;
        const float s1 = gg[r1] * rsqrtf(vvp[r1] + EPSBN);
        const float t1 = bbp[r1] - mmp[r1] * s1;
        #pragma unroll
        for (int nt = 0; nt < 7; ++nt) {
            const int c = n0 + wn * 56 + nt * 8 + tg * 2;
            float4 a = acc[mt][nt];
            if (OUT_HALF) {
                __half* C = (__half*)Cb + (size_t)z * M * N;
                *reinterpret_cast<unsigned*>(&C[(size_t)r0 * N + c]) =
                    fh2(a.x * s0 + t0, a.y * s0 + t0);
                *reinterpret_cast<unsigned*>(&C[(size_t)r1 * N + c]) =
                    fh2(a.z * s1 + t1, a.w * s1 + t1);
            } else {
                float* C = (float*)Cb + (size_t)z * M * N;
                *reinterpret_cast<float2*>(&C[(size_t)r0 * N + c]) =
                    make_float2(a.x * s0 + t0, a.y * s0 + t0);
                *reinterpret_cast<float2*>(&C[(size_t)r1 * N + c]) =
                    make_float2(a.z * s1 + t1, a.w * s1 + t1);
            }
        }
    }
}

// =====================================================================
// Depthwise 3x3 + BN; output scaled by SCALE*LOG2E, fp16
// =====================================================================
__global__ void __launch_bounds__(256) dwconv_kernel(
    const float* __restrict__ dw_w,
    const float* __restrict__ gg, const float* __restrict__ bb,
    const float* __restrict__ mm, const float* __restrict__ vv)
{
    const int bc = blockIdx.x;
    const int b  = bc >> 7;
    const int c  = bc & 127;
    const int t  = threadIdx.x;

    __shared__ float tile[30][30];
    for (int i = t; i < 900; i += 256) (&tile[0][0])[i] = 0.f;
    __syncthreads();

    const __half* in = &g_qkv[((size_t)b * QKVO_ + c) * NN_];
    for (int n = t; n < NN_; n += 256)
        tile[n / WW_ + 1][n % WW_ + 1] = __half2float(in[n]);
    __syncthreads();

    float wv[9];
    #pragma unroll
    for (int k = 0; k < 9; ++k) wv[k] = dw_w[c * 9 + k];
    const float s  = gg[c] * rsqrtf(vv[c] + EPSBN);
    const float tt = bb[c] - mm[c] * s;
    const float qs = SCALE_ * LOG2E_;

    __half* outp = &g_qdw[((size_t)b * NHKD_ + c) * NN_];
    for (int n = t; n < NN_; n += 256) {
        const int y = n / WW_, x = n % WW_;
        float a = 0.f;
        #pragma unroll
        for (int ky = 0; ky < 3; ++ky)
            #pragma unroll
            for (int kx = 0; kx < 3; ++kx)
                a = fmaf(tile[y + ky][x + kx], wv[ky * 3 + kx], a);
        outp[n] = __float2half_rn((a * s + tt) * qs);
    }
}

// =====================================================================
// Flash attention (R5 structure): fp16 m16n8k16, 112 queries (7 warps),
// key chunks of 56 (mask-free), P registers only (k padded to 64),
// double-buffered K/V (compact: ~26KB smem -> 2 blocks/SM), exp2 softmax.
// =====================================================================
__global__ void __launch_bounds__(224, 2) attn_f16(const float* __restrict__ ab)
{
    __shared__ unsigned Qf[7 * 32 * 4];        // A-frag: uint4 per (mi,lane)
    __shared__ unsigned Kf[2][7 * 32 * 2];     // B-frag: uint2 per (nt,lane)
    __shared__ unsigned Vf[2][8 * 32 * 8];     // ((nt*32+lane)*4+ks)*2+kh
    __shared__ float biasS[784];

    const int qt = blockIdx.x, h = blockIdx.y, b = blockIdx.z;
    const int q0 = qt * 112;
    const int t = threadIdx.x, lane = t & 31, wid = t >> 5;
    const int g = lane >> 2, tg = lane & 3;

    for (int i = t; i < 784; i += 224) biasS[i] = ab[h * 784 + i] * LOG2E_;

    // zero V k-pad (ks=3, kh=1) in both buffers; never written by staging
    for (int i = t; i < 512; i += 224) {
        const int bufi = i >> 8, r = i & 255;
        Vf[bufi][r * 8 + 7] = 0u;
    }

    // ---- Q staging (224 tasks): rows d=2p,2p+1 at 4 queries ----
    {
        const int p = t / 28, q4 = t % 28;
        const __half* qrow = g_qdw + ((size_t)b * NHKD_ + h * KD_ + 2 * p) * NN_
                             + q0 + q4 * 4;
        uint2 r0 = *reinterpret_cast<const uint2*>(qrow);
        uint2 r1 = *reinterpret_cast<const uint2*>(qrow + NN_);
        __half2 A0 = *reinterpret_cast<__half2*>(&r0.x);
        __half2 A1 = *reinterpret_cast<__half2*>(&r0.y);
        __half2 B0 = *reinterpret_cast<__half2*>(&r1.x);
        __half2 B1 = *reinterpret_cast<__half2*>(&r1.y);
        unsigned u[4] = { h2u(__lows2half2(A0, B0)), h2u(__highs2half2(A0, B0)),
                          h2u(__lows2half2(A1, B1)), h2u(__highs2half2(A1, B1)) };
        #pragma unroll
        for (int e = 0; e < 4; ++e) {
            const int q = q4 * 4 + e;
            const int mi = q >> 4, r = q & 15;
            Qf[(mi * 32 + (r & 7) * 4 + (p & 3)) * 4 + ((r >> 3) + 2 * (p >> 2))] = u[e];
        }
    }

    const int qa = q0 + wid * 16 + g;
    const int qya = qa / WW_, qxa = qa % WW_;
    const int qyb = (qa + 8) / WW_, qxb = (qa + 8) % WW_;

    float M0 = -1e30f, M1 = -1e30f, L0 = 0.f, L1 = 0.f;
    float4 O[8];
    #pragma unroll
    for (int i = 0; i < 8; ++i) O[i] = make_float4(0.f, 0.f, 0.f, 0.f);

    const __half* kbase = &g_qkv[((size_t)b * QKVO_ + NHKD_ + h * KD_) * NN_];
    const __half* vbase = &g_qkv[((size_t)b * QKVO_ + 2 * NHKD_ + h * DV_) * NN_];

    // K staging: 112 tasks (t < 112): d-pair p, n4
    const bool kok = t < 112;
    const int kp = kok ? t / 14 : 0, kn4 = kok ? t % 14 : 0;
    // V staging: 896 tasks (4 per thread): row d, n4
    int vd[4], vn4[4];
    #pragma unroll
    for (int j = 0; j < 4; ++j) {
        const int idx = t + 224 * j;
        vd[j] = idx / 14; vn4[j] = idx % 14;
    }

    unsigned ku[4];
    uint2 vreg[4];
    auto loadKV = [&](int c) {
        const int n0c = c * 56;
        if (kok) {
            const __half* kr = kbase + (size_t)(2 * kp) * NN_ + n0c + kn4 * 4;
            uint2 r0 = *reinterpret_cast<const uint2*>(kr);
            uint2 r1 = *reinterpret_cast<const uint2*>(kr + NN_);
            __half2 A0 = *reinterpret_cast<__half2*>(&r0.x);
            __half2 A1 = *reinterpret_cast<__half2*>(&r0.y);
            __half2 B0 = *reinterpret_cast<__half2*>(&r1.x);
            __half2 B1 = *reinterpret_cast<__half2*>(&r1.y);
            ku[0] = h2u(__lows2half2(A0, B0));  ku[1] = h2u(__highs2half2(A0, B0));
            ku[2] = h2u(__lows2half2(A1, B1)); ku[3] = h2u(__highs2half2(A1, B1));
        }
        #pragma unroll
        for (int j = 0; j < 4; ++j)
            vreg[j] = *reinterpret_cast<const uint2*>(
                &vbase[(size_t)vd[j] * NN_ + n0c + vn4[j] * 4]);
    };
    auto stsKV = [&](unsigned* kb, unsigned* vb) {
        if (kok) {
            #pragma unroll
            for (int e = 0; e < 4; ++e) {
                const int n = kn4 * 4 + e;
                kb[((n >> 3) * 32 + (n & 7) * 4 + (kp & 3)) * 2 + (kp >> 2)] = ku[e];
            }
        }
        #pragma unroll
        for (int j = 0; j < 4; ++j) {
            const int nl0 = vn4[j] * 4;
            const int tg0 = (nl0 >> 1) & 3, kh = (nl0 >> 3) & 1, ks = nl0 >> 4;
            const int base = ((vd[j] >> 3) * 32 + (vd[j] & 7) * 4);
            vb[((base + tg0) * 4 + ks) * 2 + kh]     = vreg[j].x;
            vb[((base + tg0 + 1) * 4 + ks) * 2 + kh] = vreg[j].y;
        }
    };

    loadKV(0);
    stsKV(Kf[0], Vf[0]);
    loadKV(1);
    __syncthreads();

    const uint4 qfrag = *reinterpret_cast<const uint4*>(&Qf[(wid * 32 + lane) * 4]);

    for (int c = 0; c < 14; ++c) {
        if (c + 1 < 14) {
            stsKV(Kf[(c + 1) & 1], Vf[(c + 1) & 1]);
            if (c + 2 < 14) loadKV(c + 2);
        }
        const unsigned* Kb = Kf[c & 1];
        const unsigned* Vb = Vf[c & 1];

        // ---- S = Q.K : 7 mma (k16 exact) ----
        float4 S[7];
        #pragma unroll
        for (int i = 0; i < 7; ++i) S[i] = make_float4(0.f, 0.f, 0.f, 0.f);
        #pragma unroll
        for (int nt = 0; nt < 7; ++nt) {
            uint2 kb = *reinterpret_cast<const uint2*>(&Kb[(nt * 32 + lane) * 2]);
            mma16(S[nt], qfrag, kb.x, kb.y);
        }

        // ---- bias (chunk = image rows 2c, 2c+1) ----
        const int ry0 = 2 * c, ry1 = 2 * c + 1;
        const int ba0 = abs(qya - ry0) * WW_, ba1 = abs(qya - ry1) * WW_;
        const int bb0 = abs(qyb - ry0) * WW_, bb1 = abs(qyb - ry1) * WW_;
        #pragma unroll
        for (int nt = 0; nt < 7; ++nt) {
            const int c0 = nt * 8 + tg * 2, c1 = c0 + 1;
            const int nx0 = (c0 < 28) ? c0 : c0 - 28;
            const int nx1 = (c1 < 28) ? c1 : c1 - 28;
            const bool r0b = c0 >= 28, r1b = c1 >= 28;
            S[nt].x += biasS[(r0b ? ba1 : ba0) + abs(qxa - nx0)];
            S[nt].y += biasS[(r1b ? ba1 : ba0) + abs(qxa - nx1)];
            S[nt].z += biasS[(r0b ? bb1 : bb0) + abs(qxb - nx0)];
            S[nt].w += biasS[(r1b ? bb1 : bb0) + abs(qxb - nx1)];
        }

        // ---- online softmax (log2 domain) ----
        float mx0 = -1e30f, mx1 = -1e30f;
        #pragma unroll
        for (int nt = 0; nt < 7; ++nt) {
            mx0 = fmaxf(mx0, fmaxf(S[nt].x, S[nt].y));
            mx1 = fmaxf(mx1, fmaxf(S[nt].z, S[nt].w));
        }
        mx0 = fmaxf(mx0, __shfl_xor_sync(0xffffffffu, mx0, 1));
        mx0 = fmaxf(mx0, __shfl_xor_sync(0xffffffffu, mx0, 2));
        mx1 = fmaxf(mx1, __shfl_xor_sync(0xffffffffu, mx1, 1));
        mx1 = fmaxf(mx1, __shfl_xor_sync(0xffffffffu, mx1, 2));
        const float nM0 = fmaxf(M0, mx0), nM1 = fmaxf(M1, mx1);
        const float cor0 = ex2f(M0 - nM0), cor1 = ex2f(M1 - nM1);
        M0 = nM0; M1 = nM1;
        float rs0 = 0.f, rs1 = 0.f;
        #pragma unroll
        for (int nt = 0; nt < 7; ++nt) {
            S[nt].x = ex2f(S[nt].x - nM0); rs0 += S[nt].x;
            S[nt].y = ex2f(S[nt].y - nM0); rs0 += S[nt].y;
            S[nt].z = ex2f(S[nt].z - nM1); rs1 += S[nt].z;
            S[nt].w = ex2f(S[nt].w - nM1); rs1 += S[nt].w;
        }
        rs0 += __shfl_xor_sync(0xffffffffu, rs0, 1);
        rs0 += __shfl_xor_sync(0xffffffffu, rs0, 2);
        rs1 += __shfl_xor_sync(0xffffffffu, rs1, 1);
        rs1 += __shfl_xor_sync(0xffffffffu, rs1, 2);
        L0 = L0 * cor0 + rs0;
        L1 = L1 * cor1 + rs1;
        #pragma unroll
        for (int i = 0; i < 8; ++i) {
            O[i].x *= cor0; O[i].y *= cor0;
            O[i].z *= cor1; O[i].w *= cor1;
        }

        // ---- P: registers only (A-frag packing; ks=3 upper half = pad) ----
        uint4 Pk[4];
        #pragma unroll
        for (int ks = 0; ks < 3; ++ks)
            Pk[ks] = make_uint4(fh2(S[2 * ks].x,     S[2 * ks].y),
                                fh2(S[2 * ks].z,     S[2 * ks].w),
                                fh2(S[2 * ks + 1].x, S[2 * ks + 1].y),
                                fh2(S[2 * ks + 1].z, S[2 * ks + 1].w));
        Pk[3] = make_uint4(fh2(S[6].x, S[6].y), fh2(S[6].z, S[6].w), 0u, 0u);

        // ---- O += P.V : 32 mma ----
        #pragma unroll
        for (int nt = 0; nt < 8; ++nt) {
            const unsigned* vb = &Vb[(nt * 32 + lane) * 8];
            uint4 a4 = *reinterpret_cast<const uint4*>(vb);
            uint4 b4 = *reinterpret_cast<const uint4*>(vb + 4);
            mma16(O[nt], Pk[0], a4.x, a4.y);
            mma16(O[nt], Pk[1], a4.z, a4.w);
            mma16(O[nt], Pk[2], b4.x, b4.y);
            mma16(O[nt], Pk[3], b4.z, b4.w);
        }
        __syncthreads();
    }

    // ---- normalize + relu + fp16 store ----
    const float i0 = 1.f / L0, i1 = 1.f / L1;
    __half* obase = g_att + ((size_t)b * DH_ + h * DV_) * NN_;
    #pragma unroll
    for (int nt = 0; nt < 8; ++nt) {
        const int d0 = nt * 8 + tg * 2;
        obase[(size_t)d0 * NN_ + qa]           = __float2half_rn(fmaxf(O[nt].x * i0, 0.f));
        obase[(size_t)(d0 + 1) * NN_ + qa]     = __float2half_rn(fmaxf(O[nt].y * i0, 0.f));
        obase[(size_t)d0 * NN_ + qa + 8]       = __float2half_rn(fmaxf(O[nt].z * i1, 0.f));
        obase[(size_t)(d0 + 1) * NN_ + qa + 8] = __float2half_rn(fmaxf(O[nt].w * i1, 0.f));
    }
}

// =====================================================================
// launch
// =====================================================================
extern "C" void kernel_launch(void* const* d_in, const int* in_sizes, int n_in,
                              void* d_out, int out_size)
{
    const float* x      = (const float*)d_in[0];
    const float* qkv_w  = (const float*)d_in[1];
    const float* qkv_g  = (const float*)d_in[2];
    const float* qkv_b  = (const float*)d_in[3];
    const float* qkv_m  = (const float*)d_in[4];
    const float* qkv_v  = (const float*)d_in[5];
    const float* dw_w   = (const float*)d_in[6];
    const float* dw_g   = (const float*)d_in[7];
    const float* dw_b   = (const float*)d_in[8];
    const float* dw_m   = (const float*)d_in[9];
    const float* dw_v   = (const float*)d_in[10];
    const float* ab     = (const float*)d_in[11];
    const float* proj_w = (const float*)d_in[12];
    const float* proj_g = (const float*)d_in[13];
    const float* proj_b = (const float*)d_in[14];
    const float* proj_m = (const float*)d_in[15];
    const float* proj_v = (const float*)d_in[16];
    float* out = (float*)d_out;

    void *p_qkv, *p_att, *p_x16, *p_wqkv, *p_wproj;
    cudaGetSymbolAddress(&p_qkv, g_qkv);
    cudaGetSymbolAddress(&p_att, g_att);
    cudaGetSymbolAddress(&p_x16, g_x16);
    cudaGetSymbolAddress(&p_wqkv, g_wqkv);
    cudaGetSymbolAddress(&p_wproj, g_wproj);

    // 0) prepack + transcode
    prepack_w<<<(QKVO_ * DIM_ + 255) / 256, 256>>>(qkv_w, (__half*)p_wqkv, QKVO_, DIM_);
    prepack_w<<<(DIM_ * DH_ + 255) / 256, 256>>>(proj_w, (__half*)p_wproj, DIM_, DH_);
    {
        const int n4 = BB_ * DIM_ * NN_ / 4;
        x_to_half<<<(n4 + 255) / 256, 256>>>((const float4*)x, (uint2*)p_x16, n4);
    }

    // 1) QKV 1x1 + BN : fp16 in -> fp16 out
    gemm_f16<true><<<dim3(QKVO_ / 128, NN_ / 112, BB_), 256>>>(
        (const uint4*)p_wqkv, (const __half*)p_x16, p_qkv,
        qkv_g, qkv_b, qkv_m, qkv_v, QKVO_, NN_, DIM_);

    // 2) depthwise 3x3 + BN (scaled for attention)
    dwconv_kernel<<<BB_ * NHKD_, 256>>>(dw_w, dw_g, dw_b, dw_m, dw_v);

    // 3) attention (relu folded in, fp16 out)
    attn_f16<<<dim3(NN_ / 112, HEADS_, BB_), 224>>>(ab);

    // 4) proj 1x1 + BN : fp16 in -> fp32 out
    gemm_f16<false><<<dim3(DIM_ / 128, NN_ / 112, BB_), 256>>>(
        (const uint4*)p_wproj, (const __half*)p_att, out,
        proj_g, proj_b, proj_m, proj_v, DIM_, NN_, DH_);
}

// round 11
// speedup vs baseline: 1.4968x; 1.2991x over previous
#include <cuda_runtime.h>
#include <cuda_fp16.h>
#include <cstdint>
#include <math.h>

#define BB_   32
#define DIM_  256
#define HEADS_ 8
#define KD_   16
#define DV_   64
#define NHKD_ 128
#define DH_   512
#define QKVO_ 768
#define WW_   28
#define NN_   784
#define EPSBN 1e-5f
#define SCALE_ 0.25f
#define LOG2E_ 1.4426950408889634f

// ---------------- scratch (fp16 intermediates) ----------------
__device__ __half g_qkv[(size_t)BB_ * QKVO_ * NN_ + 64];
__device__ __half g_qdw[(size_t)BB_ * NHKD_ * NN_ + 64];
__device__ __half g_att[(size_t)BB_ * DH_ * NN_ + 64];
__device__ __half g_x16[(size_t)BB_ * DIM_ * NN_ + 64];
__device__ __half g_wqkv[QKVO_ * DIM_];
__device__ __half g_wproj[DIM_ * DH_];

// ---------------- helpers ----------------
__device__ __forceinline__ float ex2f(float x) {
    float y; asm("ex2.approx.ftz.f32 %0, %1;" : "=f"(y) : "f"(x)); return y;
}
__device__ __forceinline__ unsigned fh2(float lo, float hi) {
    __half2 h = __floats2half2_rn(lo, hi);
    return *reinterpret_cast<unsigned*>(&h);
}
__device__ __forceinline__ unsigned h2u(__half2 h) {
    return *reinterpret_cast<unsigned*>(&h);
}
__device__ __forceinline__ void mma16(float4& c, const uint4& a, unsigned b0, unsigned b1) {
    asm volatile(
        "mma.sync.aligned.m16n8k16.row.col.f32.f16.f16.f32 "
        "{%0,%1,%2,%3},{%4,%5,%6,%7},{%8,%9},{%0,%1,%2,%3};"
        : "+f"(c.x), "+f"(c.y), "+f"(c.z), "+f"(c.w)
        : "r"(a.x), "r"(a.y), "r"(a.z), "r"(a.w), "r"(b0), "r"(b1));
}
__device__ __forceinline__ void ldmx2t(unsigned& r0, unsigned& r1, uint32_t addr) {
    asm volatile(
        "ldmatrix.sync.aligned.m8n8.x2.trans.shared.b16 {%0,%1}, [%2];"
        : "=r"(r0), "=r"(r1) : "r"(addr));
}

// =====================================================================
// x fp32 -> fp16 transcode
// =====================================================================
__global__ void __launch_bounds__(256) x_to_half(const float4* __restrict__ in,
                                                 uint2* __restrict__ out, int n4)
{
    const int i = blockIdx.x * 256 + threadIdx.x;
    if (i >= n4) return;
    float4 v = in[i];
    out[i] = make_uint2(fh2(v.x, v.y), fh2(v.z, v.w));
}

// =====================================================================
// Weight prepack: row-major fp32 [M,K] -> fp16 m16n8k16 A-fragment layout.
// =====================================================================
__global__ void __launch_bounds__(256) prepack_w(const float* __restrict__ W,
                                                 __half* __restrict__ P,
                                                 int M, int K)
{
    const int i = blockIdx.x * 256 + threadIdx.x;
    if (i >= M * K) return;
    const int m = i / K, k = i % K;
    const int mi = m >> 4, r = m & 15, g2 = r & 7, hf = r >> 3;
    const int ks = k >> 4, kk = k & 15;
    const int tgw = (kk >> 1) & 3, kh = kk >> 3, lo = kk & 1;
    P[((size_t)((mi * (K >> 4) + ks) * 32) + g2 * 4 + tgw) * 8 + (hf + 2 * kh) * 2 + lo]
        = __float2half_rn(W[i]);
}

// =====================================================================
// fp16 GEMM + BN. A prepacked (global->reg fragments); B staged as raw
// contiguous fp16 rows (LDG.128/STS.128), fragments via ldmatrix.x2.trans.
// Block 128(M) x 112(N) x 32(K), 256 thr, warp 32x56, double-buffered B.
// =====================================================================
#define BSTRIDE_ 120   // halves per staged row (112 + 8 pad; 240B, conflict-free)

template<bool OUT_HALF>
__global__ void __launch_bounds__(256, 2) gemm_f16(
    const uint4* __restrict__ Apk,
    const __half* __restrict__ Bsrc,
    void*        __restrict__ Cb,
    const float* __restrict__ gg, const float* __restrict__ bbp,
    const float* __restrict__ mmp, const float* __restrict__ vvp,
    int M, int N, int K)
{
    const int n0 = blockIdx.y * 112;
    const int z  = blockIdx.z;
    const __half* Bz = Bsrc + (size_t)z * K * N;

    __shared__ __align__(16) __half Bs[2][32 * BSTRIDE_];

    const int t    = threadIdx.x;
    const int lane = t & 31, wid = t >> 5;
    const int g    = lane >> 2, tg = lane & 3;
    const int wm   = wid >> 1, wn = wid & 1;
    const int nkt  = K >> 5;
    const int kt16 = K >> 4;

    float4 acc[2][7];
    #pragma unroll
    for (int i = 0; i < 2; ++i)
        #pragma unroll
        for (int j = 0; j < 7; ++j) acc[i][j] = make_float4(0.f, 0.f, 0.f, 0.f);

    // staging: 448 uint4 tasks (32 rows x 14 groups), 2 rounds
    const int kr0 = t / 14, c0 = t % 14;
    const int idx1 = t + 256;
    const bool ok1 = idx1 < 448;
    const int kr1 = ok1 ? idx1 / 14 : 0;
    const int c1  = ok1 ? idx1 % 14 : 0;

    uint4 bv0, bv1;
    auto loadB = [&](int kt) {
        bv0 = *reinterpret_cast<const uint4*>(
            Bz + (size_t)(kt * 32 + kr0) * N + n0 + c0 * 8);
        if (ok1)
            bv1 = *reinterpret_cast<const uint4*>(
                Bz + (size_t)(kt * 32 + kr1) * N + n0 + c1 * 8);
    };
    auto stsB = [&](__half* buf) {
        *reinterpret_cast<uint4*>(buf + kr0 * BSTRIDE_ + c0 * 8) = bv0;
        if (ok1)
            *reinterpret_cast<uint4*>(buf + kr1 * BSTRIDE_ + c1 * 8) = bv1;
    };

    const int mi0 = blockIdx.x * 8 + wm * 2;

    loadB(0); stsB(Bs[0]);
    if (nkt > 1) loadB(1);

    for (int kt = 0; kt < nkt; ++kt) {
        uint4 af[2][2];
        #pragma unroll
        for (int mt = 0; mt < 2; ++mt)
            #pragma unroll
            for (int ks = 0; ks < 2; ++ks)
                af[mt][ks] = Apk[(size_t)((mi0 + mt) * kt16 + kt * 2 + ks) * 32 + lane];

        __syncthreads();
        if (kt + 1 < nkt) {
            stsB(Bs[(kt + 1) & 1]);
            if (kt + 2 < nkt) loadB(kt + 2);
        }

        const __half* buf = Bs[kt & 1];
        #pragma unroll
        for (int ks = 0; ks < 2; ++ks) {
            const uint32_t rowaddr = (uint32_t)__cvta_generic_to_shared(
                buf + (ks * 16 + (lane & 15)) * BSTRIDE_ + wn * 56);
            #pragma unroll
            for (int nt = 0; nt < 7; ++nt) {
                unsigned b0, b1;
                ldmx2t(b0, b1, rowaddr + nt * 16);
                mma16(acc[0][nt], af[0][ks], b0, b1);
                mma16(acc[1][nt], af[1][ks], b0, b1);
            }
        }
    }

    // BN epilogue
    #pragma unroll
    for (int mt = 0; mt < 2; ++mt) {
        const int r0 = (mi0 + mt) * 16 + g;
        const int r1 = r0 + 8;
        const float s0 = gg[r0] * rsqrtf(vvp[r0] + EPSBN);
        const float t0 = bbp[r0] - mmp[r0] * s0;
        const float s1 = gg[r1] * rsqrtf(vvp[r1] + EPSBN);
        const float t1 = bbp[r1] - mmp[r1] * s1;
        #pragma unroll
        for (int nt = 0; nt < 7; ++nt) {
            const int c = n0 + wn * 56 + nt * 8 + tg * 2;
            float4 a = acc[mt][nt];
            if (OUT_HALF) {
                __half* C = (__half*)Cb + (size_t)z * M * N;
                *reinterpret_cast<unsigned*>(&C[(size_t)r0 * N + c]) =
                    fh2(a.x * s0 + t0, a.y * s0 + t0);
                *reinterpret_cast<unsigned*>(&C[(size_t)r1 * N + c]) =
                    fh2(a.z * s1 + t1, a.w * s1 + t1);
            } else {
                float* C = (float*)Cb + (size_t)z * M * N;
                *reinterpret_cast<float2*>(&C[(size_t)r0 * N + c]) =
                    make_float2(a.x * s0 + t0, a.y * s0 + t0);
                *reinterpret_cast<float2*>(&C[(size_t)r1 * N + c]) =
                    make_float2(a.z * s1 + t1, a.w * s1 + t1);
            }
        }
    }
}

// =====================================================================
// Depthwise 3x3 + BN; output scaled by SCALE*LOG2E, fp16
// =====================================================================
__global__ void __launch_bounds__(256) dwconv_kernel(
    const float* __restrict__ dw_w,
    const float* __restrict__ gg, const float* __restrict__ bb,
    const float* __restrict__ mm, const float* __restrict__ vv)
{
    const int bc = blockIdx.x;
    const int b  = bc >> 7;
    const int c  = bc & 127;
    const int t  = threadIdx.x;

    __shared__ float tile[30][30];
    for (int i = t; i < 900; i += 256) (&tile[0][0])[i] = 0.f;
    __syncthreads();

    const __half* in = &g_qkv[((size_t)b * QKVO_ + c) * NN_];
    for (int n = t; n < NN_; n += 256)
        tile[n / WW_ + 1][n % WW_ + 1] = __half2float(in[n]);
    __syncthreads();

    float wv[9];
    #pragma unroll
    for (int k = 0; k < 9; ++k) wv[k] = dw_w[c * 9 + k];
    const float s  = gg[c] * rsqrtf(vv[c] + EPSBN);
    const float tt = bb[c] - mm[c] * s;
    const float qs = SCALE_ * LOG2E_;

    __half* outp = &g_qdw[((size_t)b * NHKD_ + c) * NN_];
    for (int n = t; n < NN_; n += 256) {
        const int y = n / WW_, x = n % WW_;
        float a = 0.f;
        #pragma unroll
        for (int ky = 0; ky < 3; ++ky)
            #pragma unroll
            for (int kx = 0; kx < 3; ++kx)
                a = fmaf(tile[y + ky][x + kx], wv[ky * 3 + kx], a);
        outp[n] = __float2half_rn((a * s + tt) * qs);
    }
}

// =====================================================================
// Flash attention (R5 baseline, verbatim): fp16 m16n8k16, 112 queries
// (7 warps), key chunks of 56, P registers only (k padded to 64),
// double-buffered K/V, exp2 softmax, relu folded into fp16 output.
// =====================================================================
__global__ void __launch_bounds__(224, 2) attn_f16(const float* __restrict__ ab)
{
    __shared__ unsigned Qf[7 * 32 * 4];
    __shared__ unsigned Kf[2][7 * 32 * 2];
    __shared__ unsigned Vf[2][8 * 32 * 8];
    __shared__ float biasS[784];

    const int qt = blockIdx.x, h = blockIdx.y, b = blockIdx.z;
    const int q0 = qt * 112;
    const int t = threadIdx.x, lane = t & 31, wid = t >> 5;
    const int g = lane >> 2, tg = lane & 3;

    for (int i = t; i < 784; i += 224) biasS[i] = ab[h * 784 + i] * LOG2E_;

    for (int i = t; i < 512; i += 224) {
        const int bufi = i >> 8, r = i & 255;
        Vf[bufi][r * 8 + 7] = 0u;
    }

    {
        const int p = t / 28, q4 = t % 28;
        const __half* qrow = g_qdw + ((size_t)b * NHKD_ + h * KD_ + 2 * p) * NN_
                             + q0 + q4 * 4;
        uint2 r0 = *reinterpret_cast<const uint2*>(qrow);
        uint2 r1 = *reinterpret_cast<const uint2*>(qrow + NN_);
        __half2 A0 = *reinterpret_cast<__half2*>(&r0.x);
        __half2 A1 = *reinterpret_cast<__half2*>(&r0.y);
        __half2 B0 = *reinterpret_cast<__half2*>(&r1.x);
        __half2 B1 = *reinterpret_cast<__half2*>(&r1.y);
        unsigned u[4] = { h2u(__lows2half2(A0, B0)), h2u(__highs2half2(A0, B0)),
                          h2u(__lows2half2(A1, B1)), h2u(__highs2half2(A1, B1)) };
        #pragma unroll
        for (int e = 0; e < 4; ++e) {
            const int q = q4 * 4 + e;
            const int mi = q >> 4, r = q & 15;
            Qf[(mi * 32 + (r & 7) * 4 + (p & 3)) * 4 + ((r >> 3) + 2 * (p >> 2))] = u[e];
        }
    }

    const int qa = q0 + wid * 16 + g;
    const int qya = qa / WW_, qxa = qa % WW_;
    const int qyb = (qa + 8) / WW_, qxb = (qa + 8) % WW_;

    float M0 = -1e30f, M1 = -1e30f, L0 = 0.f, L1 = 0.f;
    float4 O[8];
    #pragma unroll
    for (int i = 0; i < 8; ++i) O[i] = make_float4(0.f, 0.f, 0.f, 0.f);

    const __half* kbase = &g_qkv[((size_t)b * QKVO_ + NHKD_ + h * KD_) * NN_];
    const __half* vbase = &g_qkv[((size_t)b * QKVO_ + 2 * NHKD_ + h * DV_) * NN_];

    const bool kok = t < 112;
    const int kp = kok ? t / 14 : 0, kn4 = kok ? t % 14 : 0;
    int vd[4], vn4[4];
    #pragma unroll
    for (int j = 0; j < 4; ++j) {
        const int idx = t + 224 * j;
        vd[j] = idx / 14; vn4[j] = idx % 14;
    }

    unsigned ku[4];
    uint2 vreg[4];
    auto loadKV = [&](int c) {
        const int n0c = c * 56;
        if (kok) {
            const __half* kr = kbase + (size_t)(2 * kp) * NN_ + n0c + kn4 * 4;
            uint2 r0 = *reinterpret_cast<const uint2*>(kr);
            uint2 r1 = *reinterpret_cast<const uint2*>(kr + NN_);
            __half2 A0 = *reinterpret_cast<__half2*>(&r0.x);
            __half2 A1 = *reinterpret_cast<__half2*>(&r0.y);
            __half2 B0 = *reinterpret_cast<__half2*>(&r1.x);
            __half2 B1 = *reinterpret_cast<__half2*>(&r1.y);
            ku[0] = h2u(__lows2half2(A0, B0));  ku[1] = h2u(__highs2half2(A0, B0));
            ku[2] = h2u(__lows2half2(A1, B1)); ku[3] = h2u(__highs2half2(A1, B1));
        }
        #pragma unroll
        for (int j = 0; j < 4; ++j)
            vreg[j] = *reinterpret_cast<const uint2*>(
                &vbase[(size_t)vd[j] * NN_ + n0c + vn4[j] * 4]);
    };
    auto stsKV = [&](unsigned* kb, unsigned* vb) {
        if (kok) {
            #pragma unroll
            for (int e = 0; e < 4; ++e) {
                const int n = kn4 * 4 + e;
                kb[((n >> 3) * 32 + (n & 7) * 4 + (kp & 3)) * 2 + (kp >> 2)] = ku[e];
            }
        }
        #pragma unroll
        for (int j = 0; j < 4; ++j) {
            const int nl0 = vn4[j] * 4;
            const int tg0 = (nl0 >> 1) & 3, kh = (nl0 >> 3) & 1, ks = nl0 >> 4;
            const int base = ((vd[j] >> 3) * 32 + (vd[j] & 7) * 4);
            vb[((base + tg0) * 4 + ks) * 2 + kh]     = vreg[j].x;
            vb[((base + tg0 + 1) * 4 + ks) * 2 + kh] = vreg[j].y;
        }
    };

    loadKV(0);
    stsKV(Kf[0], Vf[0]);
    loadKV(1);
    __syncthreads();

    const uint4 qfrag = *reinterpret_cast<const uint4*>(&Qf[(wid * 32 + lane) * 4]);

    for (int c = 0; c < 14; ++c) {
        if (c + 1 < 14) {
            stsKV(Kf[(c + 1) & 1], Vf[(c + 1) & 1]);
            if (c + 2 < 14) loadKV(c + 2);
        }
        const unsigned* Kb = Kf[c & 1];
        const unsigned* Vb = Vf[c & 1];

        float4 S[7];
        #pragma unroll
        for (int i = 0; i < 7; ++i) S[i] = make_float4(0.f, 0.f, 0.f, 0.f);
        #pragma unroll
        for (int nt = 0; nt < 7; ++nt) {
            uint2 kb = *reinterpret_cast<const uint2*>(&Kb[(nt * 32 + lane) * 2]);
            mma16(S[nt], qfrag, kb.x, kb.y);
        }

        const int ry0 = 2 * c, ry1 = 2 * c + 1;
        const int ba0 = abs(qya - ry0) * WW_, ba1 = abs(qya - ry1) * WW_;
        const int bb0 = abs(qyb - ry0) * WW_, bb1 = abs(qyb - ry1) * WW_;
        #pragma unroll
        for (int nt = 0; nt < 7; ++nt) {
            const int c0 = nt * 8 + tg * 2, c1 = c0 + 1;
            const int nx0 = (c0 < 28) ? c0 : c0 - 28;
            const int nx1 = (c1 < 28) ? c1 : c1 - 28;
            const bool r0b = c0 >= 28, r1b = c1 >= 28;
            S[nt].x += biasS[(r0b ? ba1 : ba0) + abs(qxa - nx0)];
            S[nt].y += biasS[(r1b ? ba1 : ba0) + abs(qxa - nx1)];
            S[nt].z += biasS[(r0b ? bb1 : bb0) + abs(qxb - nx0)];
            S[nt].w += biasS[(r1b ? bb1 : bb0) + abs(qxb - nx1)];
        }

        float mx0 = -1e30f, mx1 = -1e30f;
        #pragma unroll
        for (int nt = 0; nt < 7; ++nt) {
            mx0 = fmaxf(mx0, fmaxf(S[nt].x, S[nt].y));
            mx1 = fmaxf(mx1, fmaxf(S[nt].z, S[nt].w));
        }
        mx0 = fmaxf(mx0, __shfl_xor_sync(0xffffffffu, mx0, 1));
        mx0 = fmaxf(mx0, __shfl_xor_sync(0xffffffffu, mx0, 2));
        mx1 = fmaxf(mx1, __shfl_xor_sync(0xffffffffu, mx1, 1));
        mx1 = fmaxf(mx1, __shfl_xor_sync(0xffffffffu, mx1, 2));
        const float nM0 = fmaxf(M0, mx0), nM1 = fmaxf(M1, mx1);
        const float cor0 = ex2f(M0 - nM0), cor1 = ex2f(M1 - nM1);
        M0 = nM0; M1 = nM1;
        float rs0 = 0.f, rs1 = 0.f;
        #pragma unroll
        for (int nt = 0; nt < 7; ++nt) {
            S[nt].x = ex2f(S[nt].x - nM0); rs0 += S[nt].x;
            S[nt].y = ex2f(S[nt].y - nM0); rs0 += S[nt].y;
            S[nt].z = ex2f(S[nt].z - nM1); rs1 += S[nt].z;
            S[nt].w = ex2f(S[nt].w - nM1); rs1 += S[nt].w;
        }
        rs0 += __shfl_xor_sync(0xffffffffu, rs0, 1);
        rs0 += __shfl_xor_sync(0xffffffffu, rs0, 2);
        rs1 += __shfl_xor_sync(0xffffffffu, rs1, 1);
        rs1 += __shfl_xor_sync(0xffffffffu, rs1, 2);
        L0 = L0 * cor0 + rs0;
        L1 = L1 * cor1 + rs1;
        #pragma unroll
        for (int i = 0; i < 8; ++i) {
            O[i].x *= cor0; O[i].y *= cor0;
            O[i].z *= cor1; O[i].w *= cor1;
        }

        uint4 Pk[4];
        #pragma unroll
        for (int ks = 0; ks < 3; ++ks)
            Pk[ks] = make_uint4(fh2(S[2 * ks].x,     S[2 * ks].y),
                                fh2(S[2 * ks].z,     S[2 * ks].w),
                                fh2(S[2 * ks + 1].x, S[2 * ks + 1].y),
                                fh2(S[2 * ks + 1].z, S[2 * ks + 1].w));
        Pk[3] = make_uint4(fh2(S[6].x, S[6].y), fh2(S[6].z, S[6].w), 0u, 0u);

        #pragma unroll
        for (int nt = 0; nt < 8; ++nt) {
            const unsigned* vb = &Vb[(nt * 32 + lane) * 8];
            uint4 a4 = *reinterpret_cast<const uint4*>(vb);
            uint4 b4 = *reinterpret_cast<const uint4*>(vb + 4);
            mma16(O[nt], Pk[0], a4.x, a4.y);
            mma16(O[nt], Pk[1], a4.z, a4.w);
            mma16(O[nt], Pk[2], b4.x, b4.y);
            mma16(O[nt], Pk[3], b4.z, b4.w);
        }
        __syncthreads();
    }

    const float i0 = 1.f / L0, i1 = 1.f / L1;
    __half* obase = g_att + ((size_t)b * DH_ + h * DV_) * NN_;
    #pragma unroll
    for (int nt = 0; nt < 8; ++nt) {
        const int d0 = nt * 8 + tg * 2;
        obase[(size_t)d0 * NN_ + qa]           = __float2half_rn(fmaxf(O[nt].x * i0, 0.f));
        obase[(size_t)(d0 + 1) * NN_ + qa]     = __float2half_rn(fmaxf(O[nt].y * i0, 0.f));
        obase[(size_t)d0 * NN_ + qa + 8]       = __float2half_rn(fmaxf(O[nt].z * i1, 0.f));
        obase[(size_t)(d0 + 1) * NN_ + qa + 8] = __float2half_rn(fmaxf(O[nt].w * i1, 0.f));
    }
}

// =====================================================================
// launch
// =====================================================================
extern "C" void kernel_launch(void* const* d_in, const int* in_sizes, int n_in,
                              void* d_out, int out_size)
{
    const float* x      = (const float*)d_in[0];
    const float* qkv_w  = (const float*)d_in[1];
    const float* qkv_g  = (const float*)d_in[2];
    const float* qkv_b  = (const float*)d_in[3];
    const float* qkv_m  = (const float*)d_in[4];
    const float* qkv_v  = (const float*)d_in[5];
    const float* dw_w   = (const float*)d_in[6];
    const float* dw_g   = (const float*)d_in[7];
    const float* dw_b   = (const float*)d_in[8];
    const float* dw_m   = (const float*)d_in[9];
    const float* dw_v   = (const float*)d_in[10];
    const float* ab     = (const float*)d_in[11];
    const float* proj_w = (const float*)d_in[12];
    const float* proj_g = (const float*)d_in[13];
    const float* proj_b = (const float*)d_in[14];
    const float* proj_m = (const float*)d_in[15];
    const float* proj_v = (const float*)d_in[16];
    float* out = (float*)d_out;

    void *p_qkv, *p_att, *p_x16, *p_wqkv, *p_wproj;
    cudaGetSymbolAddress(&p_qkv, g_qkv);
    cudaGetSymbolAddress(&p_att, g_att);
    cudaGetSymbolAddress(&p_x16, g_x16);
    cudaGetSymbolAddress(&p_wqkv, g_wqkv);
    cudaGetSymbolAddress(&p_wproj, g_wproj);

    // 0) prepack + transcode
    prepack_w<<<(QKVO_ * DIM_ + 255) / 256, 256>>>(qkv_w, (__half*)p_wqkv, QKVO_, DIM_);
    prepack_w<<<(DIM_ * DH_ + 255) / 256, 256>>>(proj_w, (__half*)p_wproj, DIM_, DH_);
    {
        const int n4 = BB_ * DIM_ * NN_ / 4;
        x_to_half<<<(n4 + 255) / 256, 256>>>((const float4*)x, (uint2*)p_x16, n4);
    }

    // 1) QKV 1x1 + BN : fp16 in -> fp16 out
    gemm_f16<true><<<dim3(QKVO_ / 128, NN_ / 112, BB_), 256>>>(
        (const uint4*)p_wqkv, (const __half*)p_x16, p_qkv,
        qkv_g, qkv_b, qkv_m, qkv_v, QKVO_, NN_, DIM_);

    // 2) depthwise 3x3 + BN (scaled for attention)
    dwconv_kernel<<<BB_ * NHKD_, 256>>>(dw_w, dw_g, dw_b, dw_m, dw_v);

    // 3) attention (relu folded in, fp16 out)
    attn_f16<<<dim3(NN_ / 112, HEADS_, BB_), 224>>>(ab);

    // 4) proj 1x1 + BN : fp16 in -> fp32 out
    gemm_f16<false><<<dim3(DIM_ / 128, NN_ / 112, BB_), 256>>>(
        (const uint4*)p_wproj, (const __half*)p_att, out,
        proj_g, proj_b, proj_m, proj_v, DIM_, NN_, DH_);
}

// round 12
// speedup vs baseline: 2.0326x; 1.3579x over previous
#include <cuda_runtime.h>
#include <cuda_fp16.h>
#include <cstdint>
#include <math.h>

#define BB_   32
#define DIM_  256
#define HEADS_ 8
#define KD_   16
#define DV_   64
#define NHKD_ 128
#define DH_   512
#define QKVO_ 768
#define WW_   28
#define NN_   784
#define EPSBN 1e-5f
#define SCALE_ 0.25f
#define LOG2E_ 1.4426950408889634f

// ---------------- scratch (fp16 intermediates) ----------------
__device__ __half g_qkv[(size_t)BB_ * QKVO_ * NN_ + 64];
__device__ __half g_qdw[(size_t)BB_ * NHKD_ * NN_ + 64];
__device__ __half g_att[(size_t)BB_ * DH_ * NN_ + 64];
__device__ __half g_x16[(size_t)BB_ * DIM_ * NN_ + 64];
__device__ __half g_wqkv[QKVO_ * DIM_];
__device__ __half g_wproj[DIM_ * DH_];

// ---------------- helpers ----------------
__device__ __forceinline__ float ex2f(float x) {
    float y; asm("ex2.approx.ftz.f32 %0, %1;" : "=f"(y) : "f"(x)); return y;
}
__device__ __forceinline__ unsigned fh2(float lo, float hi) {
    __half2 h = __floats2half2_rn(lo, hi);
    return *reinterpret_cast<unsigned*>(&h);
}
__device__ __forceinline__ unsigned h2u(__half2 h) {
    return *reinterpret_cast<unsigned*>(&h);
}
__device__ __forceinline__ void mma16(float4& c, const uint4& a, unsigned b0, unsigned b1) {
    asm volatile(
        "mma.sync.aligned.m16n8k16.row.col.f32.f16.f16.f32 "
        "{%0,%1,%2,%3},{%4,%5,%6,%7},{%8,%9},{%0,%1,%2,%3};"
        : "+f"(c.x), "+f"(c.y), "+f"(c.z), "+f"(c.w)
        : "r"(a.x), "r"(a.y), "r"(a.z), "r"(a.w), "r"(b0), "r"(b1));
}
__device__ __forceinline__ void ldmx2t(unsigned& r0, unsigned& r1, uint32_t addr) {
    asm volatile(
        "ldmatrix.sync.aligned.m8n8.x2.trans.shared.b16 {%0,%1}, [%2];"
        : "=r"(r0), "=r"(r1) : "r"(addr));
}
__device__ __forceinline__ void ldmx4(unsigned& r0, unsigned& r1,
                                      unsigned& r2, unsigned& r3, uint32_t addr) {
    asm volatile(
        "ldmatrix.sync.aligned.m8n8.x4.shared.b16 {%0,%1,%2,%3}, [%4];"
        : "=r"(r0), "=r"(r1), "=r"(r2), "=r"(r3) : "r"(addr));
}
__device__ __forceinline__ uint32_t s2u(const void* p) {
    return (uint32_t)__cvta_generic_to_shared(p);
}
__device__ __forceinline__ void cpa16(uint32_t s, const void* g) {
    asm volatile("cp.async.cg.shared.global [%0], [%1], 16;" :: "r"(s), "l"(g));
}
__device__ __forceinline__ void cpa_commit() {
    asm volatile("cp.async.commit_group;" ::: "memory");
}
__device__ __forceinline__ void cpa_wait1() {
    asm volatile("cp.async.wait_group 1;" ::: "memory");
}
__device__ __forceinline__ void cpa_wait0() {
    asm volatile("cp.async.wait_group 0;" ::: "memory");
}

// =====================================================================
// x fp32 -> fp16 transcode
// =====================================================================
__global__ void __launch_bounds__(256) x_to_half(const float4* __restrict__ in,
                                                 uint2* __restrict__ out, int n4)
{
    const int i = blockIdx.x * 256 + threadIdx.x;
    if (i >= n4) return;
    float4 v = in[i];
    out[i] = make_uint2(fh2(v.x, v.y), fh2(v.z, v.w));
}

// =====================================================================
// Weight prepack: row-major fp32 [M,K] -> fp16 m16n8k16 A-fragment layout.
// =====================================================================
__global__ void __launch_bounds__(256) prepack_w(const float* __restrict__ W,
                                                 __half* __restrict__ P,
                                                 int M, int K)
{
    const int i = blockIdx.x * 256 + threadIdx.x;
    if (i >= M * K) return;
    const int m = i / K, k = i % K;
    const int mi = m >> 4, r = m & 15, g2 = r & 7, hf = r >> 3;
    const int ks = k >> 4, kk = k & 15;
    const int tgw = (kk >> 1) & 3, kh = kk >> 3, lo = kk & 1;
    P[((size_t)((mi * (K >> 4) + ks) * 32) + g2 * 4 + tgw) * 8 + (hf + 2 * kh) * 2 + lo]
        = __float2half_rn(W[i]);
}

// =====================================================================
// fp16 GEMM + BN. A prepacked (global->reg fragments); B staged as raw
// fp16 rows via cp.async (3-buffer ring), fragments via ldmatrix.x2.trans.
// Block 128(M) x 112(N) x 32(K), 256 thr, warp 32x56.
// =====================================================================
#define BSTRIDE_ 120   // halves per staged row (112 + 8 pad; 240B, conflict-free)

template<bool OUT_HALF>
__global__ void __launch_bounds__(256, 2) gemm_f16(
    const uint4* __restrict__ Apk,
    const __half* __restrict__ Bsrc,
    void*        __restrict__ Cb,
    const float* __restrict__ gg, const float* __restrict__ bbp,
    const float* __restrict__ mmp, const float* __restrict__ vvp,
    int M, int N, int K)
{
    const int n0 = blockIdx.y * 112;
    const int z  = blockIdx.z;
    const __half* Bz = Bsrc + (size_t)z * K * N;

    __shared__ __align__(16) __half Bs[3][32 * BSTRIDE_];

    const int t    = threadIdx.x;
    const int lane = t & 31, wid = t >> 5;
    const int g    = lane >> 2, tg = lane & 3;
    const int wm   = wid >> 1, wn = wid & 1;
    const int nkt  = K >> 5;
    const int kt16 = K >> 4;

    float4 acc[2][7];
    #pragma unroll
    for (int i = 0; i < 2; ++i)
        #pragma unroll
        for (int j = 0; j < 7; ++j) acc[i][j] = make_float4(0.f, 0.f, 0.f, 0.f);

    // staging: 448 cp.async tasks (32 rows x 14 groups of 16B), 2 rounds
    const int kr0 = t / 14, c0 = t % 14;
    const int idx1 = t + 256;
    const bool ok1 = idx1 < 448;
    const int kr1 = ok1 ? idx1 / 14 : 0;
    const int c1  = ok1 ? idx1 % 14 : 0;

    auto issue = [&](int kt) {
        __half* buf = Bs[kt % 3];
        cpa16(s2u(buf + kr0 * BSTRIDE_ + c0 * 8),
              Bz + (size_t)(kt * 32 + kr0) * N + n0 + c0 * 8);
        if (ok1)
            cpa16(s2u(buf + kr1 * BSTRIDE_ + c1 * 8),
                  Bz + (size_t)(kt * 32 + kr1) * N + n0 + c1 * 8);
        cpa_commit();
    };

    const int mi0 = blockIdx.x * 8 + wm * 2;

    issue(0);
    if (nkt > 1) issue(1);

    for (int kt = 0; kt < nkt; ++kt) {
        uint4 af[2][2];
        #pragma unroll
        for (int mt = 0; mt < 2; ++mt)
            #pragma unroll
            for (int ks = 0; ks < 2; ++ks)
                af[mt][ks] = Apk[(size_t)((mi0 + mt) * kt16 + kt * 2 + ks) * 32 + lane];

        if (kt + 1 < nkt) cpa_wait1(); else cpa_wait0();
        __syncthreads();
        if (kt + 2 < nkt) issue(kt + 2);

        const __half* buf = Bs[kt % 3];
        #pragma unroll
        for (int ks = 0; ks < 2; ++ks) {
            const uint32_t rowaddr = s2u(
                buf + (ks * 16 + (lane & 15)) * BSTRIDE_ + wn * 56);
            #pragma unroll
            for (int nt = 0; nt < 7; ++nt) {
                unsigned b0, b1;
                ldmx2t(b0, b1, rowaddr + nt * 16);
                mma16(acc[0][nt], af[0][ks], b0, b1);
                mma16(acc[1][nt], af[1][ks], b0, b1);
            }
        }
    }

    // BN epilogue
    #pragma unroll
    for (int mt = 0; mt < 2; ++mt) {
        const int r0 = (mi0 + mt) * 16 + g;
        const int r1 = r0 + 8;
        const float s0 = gg[r0] * rsqrtf(vvp[r0] + EPSBN);
        const float t0 = bbp[r0] - mmp[r0] * s0;
        const float s1 = gg[r1] * rsqrtf(vvp[r1] + EPSBN);
        const float t1 = bbp[r1] - mmp[r1] * s1;
        #pragma unroll
        for (int nt = 0; nt < 7; ++nt) {
            const int c = n0 + wn * 56 + nt * 8 + tg * 2;
            float4 a = acc[mt][nt];
            if (OUT_HALF) {
                __half* C = (__half*)Cb + (size_t)z * M * N;
                *reinterpret_cast<unsigned*>(&C[(size_t)r0 * N + c]) =
                    fh2(a.x * s0 + t0, a.y * s0 + t0);
                *reinterpret_cast<unsigned*>(&C[(size_t)r1 * N + c]) =
                    fh2(a.z * s1 + t1, a.w * s1 + t1);
            } else {
                float* C = (float*)Cb + (size_t)z * M * N;
                *reinterpret_cast<float2*>(&C[(size_t)r0 * N + c]) =
                    make_float2(a.x * s0 + t0, a.y * s0 + t0);
                *reinterpret_cast<float2*>(&C[(size_t)r1 * N + c]) =
                    make_float2(a.z * s1 + t1, a.w * s1 + t1);
            }
        }
    }
}

// =====================================================================
// Depthwise 3x3 + BN; output scaled by SCALE*LOG2E, fp16
// =====================================================================
__global__ void __launch_bounds__(256) dwconv_kernel(
    const float* __restrict__ dw_w,
    const float* __restrict__ gg, const float* __restrict__ bb,
    const float* __restrict__ mm, const float* __restrict__ vv)
{
    const int bc = blockIdx.x;
    const int b  = bc >> 7;
    const int c  = bc & 127;
    const int t  = threadIdx.x;

    __shared__ float tile[30][30];
    for (int i = t; i < 900; i += 256) (&tile[0][0])[i] = 0.f;
    __syncthreads();

    const __half* in = &g_qkv[((size_t)b * QKVO_ + c) * NN_];
    for (int n = t; n < NN_; n += 256)
        tile[n / WW_ + 1][n % WW_ + 1] = __half2float(in[n]);
    __syncthreads();

    float wv[9];
    #pragma unroll
    for (int k = 0; k < 9; ++k) wv[k] = dw_w[c * 9 + k];
    const float s  = gg[c] * rsqrtf(vv[c] + EPSBN);
    const float tt = bb[c] - mm[c] * s;
    const float qs = SCALE_ * LOG2E_;

    __half* outp = &g_qdw[((size_t)b * NHKD_ + c) * NN_];
    for (int n = t; n < NN_; n += 256) {
        const int y = n / WW_, x = n % WW_;
        float a = 0.f;
        #pragma unroll
        for (int ky = 0; ky < 3; ++ky)
            #pragma unroll
            for (int kx = 0; kx < 3; ++kx)
                a = fmaf(tile[y + ky][x + kx], wv[ky * 3 + kx], a);
        outp[n] = __float2half_rn((a * s + tt) * qs);
    }
}

// =====================================================================
// Flash attention: fp16 m16n8k16, 112 queries (7 warps), 56-key chunks.
// K/V staged as RAW rows (stride 72 halves) via cp.async 3-buffer ring;
// S B-frags via ldmatrix.x2.trans, PV B-frags via ldmatrix.x4 non-trans.
// P registers only (k padded to 64), exp2 softmax, relu folded in.
// =====================================================================
__global__ void __launch_bounds__(224, 2) attn_f16(const float* __restrict__ ab)
{
    __shared__ __align__(16) __half Kraw[3][16 * 72];
    __shared__ __align__(16) __half Vraw[3][64 * 72];
    __shared__ unsigned Qf[7 * 32 * 4];
    __shared__ float biasS[784];

    const int qt = blockIdx.x, h = blockIdx.y, b = blockIdx.z;
    const int q0 = qt * 112;
    const int t = threadIdx.x, lane = t & 31, wid = t >> 5;
    const int g = lane >> 2, tg = lane & 3;

    for (int i = t; i < 784; i += 224) biasS[i] = ab[h * 784 + i] * LOG2E_;

    // zero V pad keys 56..63 in all 3 buffers (never written by cp.async)
    for (int i = t; i < 192; i += 224) {
        const int bufi = i / 64, row = i % 64;
        *reinterpret_cast<uint4*>(&Vraw[bufi][row * 72 + 56]) =
            make_uint4(0u, 0u, 0u, 0u);
    }

    // ---- Q staging (224 tasks): rows d=2p,2p+1 at 4 queries, A-frag layout ----
    {
        const int p = t / 28, q4 = t % 28;
        const __half* qrow = g_qdw + ((size_t)b * NHKD_ + h * KD_ + 2 * p) * NN_
                             + q0 + q4 * 4;
        uint2 r0 = *reinterpret_cast<const uint2*>(qrow);
        uint2 r1 = *reinterpret_cast<const uint2*>(qrow + NN_);
        __half2 A0 = *reinterpret_cast<__half2*>(&r0.x);
        __half2 A1 = *reinterpret_cast<__half2*>(&r0.y);
        __half2 B0 = *reinterpret_cast<__half2*>(&r1.x);
        __half2 B1 = *reinterpret_cast<__half2*>(&r1.y);
        unsigned u[4] = { h2u(__lows2half2(A0, B0)), h2u(__highs2half2(A0, B0)),
                          h2u(__lows2half2(A1, B1)), h2u(__highs2half2(A1, B1)) };
        #pragma unroll
        for (int e = 0; e < 4; ++e) {
            const int q = q4 * 4 + e;
            const int mi = q >> 4, r = q & 15;
            Qf[(mi * 32 + (r & 7) * 4 + (p & 3)) * 4 + ((r >> 3) + 2 * (p >> 2))] = u[e];
        }
    }

    const int qa = q0 + wid * 16 + g;
    const int qya = qa / WW_, qxa = qa % WW_;
    const int qyb = (qa + 8) / WW_, qxb = (qa + 8) % WW_;

    float M0 = -1e30f, M1 = -1e30f, L0 = 0.f, L1 = 0.f;
    float4 O[8];
    #pragma unroll
    for (int i = 0; i < 8; ++i) O[i] = make_float4(0.f, 0.f, 0.f, 0.f);

    const __half* kbase = &g_qkv[((size_t)b * QKVO_ + NHKD_ + h * KD_) * NN_];
    const __half* vbase = &g_qkv[((size_t)b * QKVO_ + 2 * NHKD_ + h * DV_) * NN_];

    // cp.async staging tasks: K 112 (16 rows x 7 groups), V 448 (64 x 7)
    const bool kok = t < 112;
    const int krow = kok ? t / 7 : 0, kgrp = kok ? t % 7 : 0;
    int vrow[2], vgrp[2];
    #pragma unroll
    for (int j = 0; j < 2; ++j) {
        const int idx = t + 224 * j;
        vrow[j] = idx / 7; vgrp[j] = idx % 7;
    }

    auto issue = [&](int c) {
        const int buf = c % 3;
        const int n0c = c * 56;
        if (kok)
            cpa16(s2u(&Kraw[buf][krow * 72 + kgrp * 8]),
                  kbase + (size_t)krow * NN_ + n0c + kgrp * 8);
        #pragma unroll
        for (int j = 0; j < 2; ++j)
            cpa16(s2u(&Vraw[buf][vrow[j] * 72 + vgrp[j] * 8]),
                  vbase + (size_t)vrow[j] * NN_ + n0c + vgrp[j] * 8);
        cpa_commit();
    };

    issue(0);
    issue(1);
    __syncthreads();   // Q staging + pad zero visible

    const uint4 qfrag = *reinterpret_cast<const uint4*>(&Qf[(wid * 32 + lane) * 4]);

    for (int c = 0; c < 14; ++c) {
        if (c < 13) cpa_wait1(); else cpa_wait0();
        __syncthreads();
        if (c + 2 < 14) issue(c + 2);   // target buf (c+2)%3 == (c-1)%3: free

        const __half* Kb = Kraw[c % 3];
        const __half* Vb = Vraw[c % 3];

        // ---- S = Q.K : ldmatrix.x2.trans + 7 mma ----
        float4 S[7];
        #pragma unroll
        for (int i = 0; i < 7; ++i) S[i] = make_float4(0.f, 0.f, 0.f, 0.f);
        {
            const uint32_t krowaddr = s2u(Kb + (lane & 15) * 72);
            #pragma unroll
            for (int nt = 0; nt < 7; ++nt) {
                unsigned b0, b1;
                ldmx2t(b0, b1, krowaddr + nt * 16);
                mma16(S[nt], qfrag, b0, b1);
            }
        }

        // ---- bias (chunk = image rows 2c, 2c+1) ----
        const int ry0 = 2 * c, ry1 = 2 * c + 1;
        const int ba0 = abs(qya - ry0) * WW_, ba1 = abs(qya - ry1) * WW_;
        const int bb0 = abs(qyb - ry0) * WW_, bb1 = abs(qyb - ry1) * WW_;
        #pragma unroll
        for (int nt = 0; nt < 7; ++nt) {
            const int c0 = nt * 8 + tg * 2, c1 = c0 + 1;
            const int nx0 = (c0 < 28) ? c0 : c0 - 28;
            const int nx1 = (c1 < 28) ? c1 : c1 - 28;
            const bool r0b = c0 >= 28, r1b = c1 >= 28;
            S[nt].x += biasS[(r0b ? ba1 : ba0) + abs(qxa - nx0)];
            S[nt].y += biasS[(r1b ? ba1 : ba0) + abs(qxa - nx1)];
            S[nt].z += biasS[(r0b ? bb1 : bb0) + abs(qxb - nx0)];
            S[nt].w += biasS[(r1b ? bb1 : bb0) + abs(qxb - nx1)];
        }

        // ---- online softmax (log2 domain) ----
        float mx0 = -1e30f, mx1 = -1e30f;
        #pragma unroll
        for (int nt = 0; nt < 7; ++nt) {
            mx0 = fmaxf(mx0, fmaxf(S[nt].x, S[nt].y));
            mx1 = fmaxf(mx1, fmaxf(S[nt].z, S[nt].w));
        }
        mx0 = fmaxf(mx0, __shfl_xor_sync(0xffffffffu, mx0, 1));
        mx0 = fmaxf(mx0, __shfl_xor_sync(0xffffffffu, mx0, 2));
        mx1 = fmaxf(mx1, __shfl_xor_sync(0xffffffffu, mx1, 1));
        mx1 = fmaxf(mx1, __shfl_xor_sync(0xffffffffu, mx1, 2));
        const float nM0 = fmaxf(M0, mx0), nM1 = fmaxf(M1, mx1);
        const float cor0 = ex2f(M0 - nM0), cor1 = ex2f(M1 - nM1);
        M0 = nM0; M1 = nM1;
        float rs0 = 0.f, rs1 = 0.f;
        #pragma unroll
        for (int nt = 0; nt < 7; ++nt) {
            S[nt].x = ex2f(S[nt].x - nM0); rs0 += S[nt].x;
            S[nt].y = ex2f(S[nt].y - nM0); rs0 += S[nt].y;
            S[nt].z = ex2f(S[nt].z - nM1); rs1 += S[nt].z;
            S[nt].w = ex2f(S[nt].w - nM1); rs1 += S[nt].w;
        }
        rs0 += __shfl_xor_sync(0xffffffffu, rs0, 1);
        rs0 += __shfl_xor_sync(0xffffffffu, rs0, 2);
        rs1 += __shfl_xor_sync(0xffffffffu, rs1, 1);
        rs1 += __shfl_xor_sync(0xffffffffu, rs1, 2);
        L0 = L0 * cor0 + rs0;
        L1 = L1 * cor1 + rs1;
        #pragma unroll
        for (int i = 0; i < 8; ++i) {
            O[i].x *= cor0; O[i].y *= cor0;
            O[i].z *= cor1; O[i].w *= cor1;
        }

        // ---- P: registers only (A-frag packing; keys 56..63 = zero pad) ----
        uint4 Pk[4];
        #pragma unroll
        for (int ks = 0; ks < 3; ++ks)
            Pk[ks] = make_uint4(fh2(S[2 * ks].x,     S[2 * ks].y),
                                fh2(S[2 * ks].z,     S[2 * ks].w),
                                fh2(S[2 * ks + 1].x, S[2 * ks + 1].y),
                                fh2(S[2 * ks + 1].z, S[2 * ks + 1].w));
        Pk[3] = make_uint4(fh2(S[6].x, S[6].y), fh2(S[6].z, S[6].w), 0u, 0u);

        // ---- O += P.V : ldmatrix.x4 non-trans + 32 mma ----
        {
            const uint32_t vladdr = s2u(Vb) + (lane & 7) * 144 + (lane >> 3) * 16;
            #pragma unroll
            for (int nt = 0; nt < 8; ++nt) {
                const uint32_t a0 = vladdr + nt * 8 * 144;
                unsigned r0, r1, r2, r3;
                ldmx4(r0, r1, r2, r3, a0);
                mma16(O[nt], Pk[0], r0, r1);
                mma16(O[nt], Pk[1], r2, r3);
                ldmx4(r0, r1, r2, r3, a0 + 64);
                mma16(O[nt], Pk[2], r0, r1);
                mma16(O[nt], Pk[3], r2, r3);
            }
        }
    }

    // ---- normalize + relu + fp16 store ----
    const float i0 = 1.f / L0, i1 = 1.f / L1;
    __half* obase = g_att + ((size_t)b * DH_ + h * DV_) * NN_;
    #pragma unroll
    for (int nt = 0; nt < 8; ++nt) {
        const int d0 = nt * 8 + tg * 2;
        obase[(size_t)d0 * NN_ + qa]           = __float2half_rn(fmaxf(O[nt].x * i0, 0.f));
        obase[(size_t)(d0 + 1) * NN_ + qa]     = __float2half_rn(fmaxf(O[nt].y * i0, 0.f));
        obase[(size_t)d0 * NN_ + qa + 8]       = __float2half_rn(fmaxf(O[nt].z * i1, 0.f));
        obase[(size_t)(d0 + 1) * NN_ + qa + 8] = __float2half_rn(fmaxf(O[nt].w * i1, 0.f));
    }
}

// =====================================================================
// launch
// =====================================================================
extern "C" void kernel_launch(void* const* d_in, const int* in_sizes, int n_in,
                              void* d_out, int out_size)
{
    const float* x      = (const float*)d_in[0];
    const float* qkv_w  = (const float*)d_in[1];
    const float* qkv_g  = (const float*)d_in[2];
    const float* qkv_b  = (const float*)d_in[3];
    const float* qkv_m  = (const float*)d_in[4];
    const float* qkv_v  = (const float*)d_in[5];
    const float* dw_w   = (const float*)d_in[6];
    const float* dw_g   = (const float*)d_in[7];
    const float* dw_b   = (const float*)d_in[8];
    const float* dw_m   = (const float*)d_in[9];
    const float* dw_v   = (const float*)d_in[10];
    const float* ab     = (const float*)d_in[11];
    const float* proj_w = (const float*)d_in[12];
    const float* proj_g = (const float*)d_in[13];
    const float* proj_b = (const float*)d_in[14];
    const float* proj_m = (const float*)d_in[15];
    const float* proj_v = (const float*)d_in[16];
    float* out = (float*)d_out;

    void *p_qkv, *p_att, *p_x16, *p_wqkv, *p_wproj;
    cudaGetSymbolAddress(&p_qkv, g_qkv);
    cudaGetSymbolAddress(&p_att, g_att);
    cudaGetSymbolAddress(&p_x16, g_x16);
    cudaGetSymbolAddress(&p_wqkv, g_wqkv);
    cudaGetSymbolAddress(&p_wproj, g_wproj);

    // 0) prepack + transcode
    prepack_w<<<(QKVO_ * DIM_ + 255) / 256, 256>>>(qkv_w, (__half*)p_wqkv, QKVO_, DIM_);
    prepack_w<<<(DIM_ * DH_ + 255) / 256, 256>>>(proj_w, (__half*)p_wproj, DIM_, DH_);
    {
        const int n4 = BB_ * DIM_ * NN_ / 4;
        x_to_half<<<(n4 + 255) / 256, 256>>>((const float4*)x, (uint2*)p_x16, n4);
    }

    // 1) QKV 1x1 + BN : fp16 in -> fp16 out
    gemm_f16<true><<<dim3(QKVO_ / 128, NN_ / 112, BB_), 256>>>(
        (const uint4*)p_wqkv, (const __half*)p_x16, p_qkv,
        qkv_g, qkv_b, qkv_m, qkv_v, QKVO_, NN_, DIM_);

    // 2) depthwise 3x3 + BN (scaled for attention)
    dwconv_kernel<<<BB_ * NHKD_, 256>>>(dw_w, dw_g, dw_b, dw_m, dw_v);

    // 3) attention (relu folded in, fp16 out)
    attn_f16<<<dim3(NN_ / 112, HEADS_, BB_), 224>>>(ab);

    // 4) proj 1x1 + BN : fp16 in -> fp32 out
    gemm_f16<false><<<dim3(DIM_ / 128, NN_ / 112, BB_), 256>>>(
        (const uint4*)p_wproj, (const __half*)p_att, out,
        proj_g, proj_b, proj_m, proj_v, DIM_, NN_, DH_);
}